// round 13
// baseline (speedup 1.0000x reference)
#include <cuda_runtime.h>
#include <cuda_fp16.h>
#include <cuda_bf16.h>
#include <math.h>
#include <stdint.h>

// ---------------------------------------------------------------------------
// Problem constants
// ---------------------------------------------------------------------------
#define NUM_HEADS   8
#define NUM_CHUNKS  50000
#define INPUT_DIM   768
#define HIDDEN_DIM  512
#define OUTPUT_DIM  256
#define NUM_CELLS   2048
#define MAX_LEN     64
#define HEAD_DIM    64
#define QKV_DIM     1536
#define M_PAD       50048              // 391 * 128
#define SPLITK      4

// mma GEMM geometry (k-chunk 64, swizzled smem, 3 stages, 2 CTA/SM)
#define CHUNK_K     64
#define NCHUNKS     12                 // single fp16 pass: 768/64
#define NCHUNKS_O   8                  // final projection: 512/64
#define TILE_BYTES  (128 * 128)        // 16384 (128 rows x 128B swizzled)
#define STAGE_B     (2 * TILE_BYTES)   // 32768
#define SMEM_MMA    (3 * STAGE_B)      // 98304

// ---------------------------------------------------------------------------
// Device-global scratch (allocation-free contract)
// ---------------------------------------------------------------------------
__device__ __align__(1024) __half g_Ahi[(size_t)M_PAD * INPUT_DIM];
__device__ __align__(1024) __half g_Bhi[QKV_DIM * INPUT_DIM];
__device__ __align__(1024) __half g_QKV[(size_t)NUM_CHUNKS * QKV_DIM];
__device__ __align__(1024) __half g_pooled[NUM_CELLS * HIDDEN_DIM];
__device__ __align__(1024) __half g_Wfinalh[OUTPUT_DIM * HIDDEN_DIM];
__device__ __align__(256) float g_beff[QKV_DIM];
__device__ __align__(256) float g_bfinal[OUTPUT_DIM];
__device__ __align__(256) float g_WeffPart[SPLITK * QKV_DIM * INPUT_DIM];
__device__ __align__(256) float g_WfinalPart[SPLITK * OUTPUT_DIM * HIDDEN_DIM];
__device__ int g_idx_is64;
__device__ int g_len_is64;

// ---------------------------------------------------------------------------
// PTX helpers (plain-sm_80-level: safe for non-'a' ptx target)
// ---------------------------------------------------------------------------
__device__ __forceinline__ uint32_t smem_u32(const void* p) {
    uint32_t a;
    asm("{ .reg .u64 t; cvta.to.shared.u64 t, %1; cvt.u32.u64 %0, t; }"
        : "=r"(a) : "l"(p));
    return a;
}
__device__ __forceinline__ void cp16(uint32_t d, const void* s) {
    asm volatile("cp.async.cg.shared.global [%0], [%1], 16;" :: "r"(d), "l"(s));
}
__device__ __forceinline__ void cp_commit() {
    asm volatile("cp.async.commit_group;" ::: "memory");
}
template <int N>
__device__ __forceinline__ void cp_wait() {
    asm volatile("cp.async.wait_group %0;" :: "n"(N) : "memory");
}
__device__ __forceinline__ void ldsm4(uint32_t& r0, uint32_t& r1, uint32_t& r2,
                                      uint32_t& r3, uint32_t a) {
    asm volatile("ldmatrix.sync.aligned.m8n8.x4.shared.b16 {%0,%1,%2,%3}, [%4];"
                 : "=r"(r0), "=r"(r1), "=r"(r2), "=r"(r3) : "r"(a));
}
__device__ __forceinline__ void mma16816(float* c, uint32_t a0, uint32_t a1,
                                         uint32_t a2, uint32_t a3,
                                         uint32_t b0, uint32_t b1) {
    asm volatile("mma.sync.aligned.m16n8k16.row.col.f32.f16.f16.f32 "
                 "{%0,%1,%2,%3}, {%4,%5,%6,%7}, {%8,%9}, {%0,%1,%2,%3};"
                 : "+f"(c[0]), "+f"(c[1]), "+f"(c[2]), "+f"(c[3])
                 : "r"(a0), "r"(a1), "r"(a2), "r"(a3), "r"(b0), "r"(b1));
}
__device__ __forceinline__ uint32_t packh2(float a, float b) {
    __half2 h = __floats2half2_rn(a, b);
    return *(uint32_t*)&h;
}

// ---------------------------------------------------------------------------
// dtype detection + combined biases (merged, one launch)
// ---------------------------------------------------------------------------
__global__ void setup_kernel(const int* __restrict__ iw, const int* __restrict__ lw,
                             const float* __restrict__ W_in, const float* __restrict__ b_in,
                             const float* __restrict__ bq, const float* __restrict__ bk,
                             const float* __restrict__ bv, const float* __restrict__ Wout,
                             const float* __restrict__ bo, const float* __restrict__ bout,
                             float* __restrict__ beff, float* __restrict__ bfinal) {
    int i = blockIdx.x * blockDim.x + threadIdx.x;
    if (i == QKV_DIM + OUTPUT_DIM) {
        int oi = 0, ol = 0;
        for (int k = 0; k < 256; k++) oi |= iw[2 * k + 1];
        for (int k = 0; k < 256; k++) ol |= lw[2 * k + 1];
        g_idx_is64 = (oi == 0) ? 1 : 0;
        g_len_is64 = (ol == 0) ? 1 : 0;
        return;
    }
    if (i < QKV_DIM) {
        const float* bs = (i < HIDDEN_DIM) ? bq : (i < 2 * HIDDEN_DIM ? bk : bv);
        const float* w = W_in + (size_t)i * HIDDEN_DIM;
        float s = 0.f;
        for (int k = 0; k < HIDDEN_DIM; k++) s = fmaf(w[k], bs[k], s);
        beff[i] = s + b_in[i];
    } else if (i < QKV_DIM + OUTPUT_DIM) {
        int o = i - QKV_DIM;
        const float* w = Wout + (size_t)o * HIDDEN_DIM;
        float s = 0.f;
        for (int k = 0; k < HIDDEN_DIM; k++) s = fmaf(w[k], bo[k], s);
        bfinal[o] = s + bout[o];
    }
}

// ---------------------------------------------------------------------------
// SIMT tile GEMM body (128x128, 8x8/thread). Small split-K GEMMs.
// ---------------------------------------------------------------------------
__device__ __forceinline__ void sgemm_tile_nn(int Klen, int lda, int ldb, int ldc,
                                              const float* __restrict__ A,
                                              const float* __restrict__ B,
                                              float* __restrict__ C, int bm, int bn) {
    __shared__ float As[8][128];
    __shared__ float Bs[8][128];
    const int tid = threadIdx.x;
    const int tx = tid & 15, ty = tid >> 4;
    float acc[8][8];
#pragma unroll
    for (int i = 0; i < 8; i++)
#pragma unroll
        for (int j = 0; j < 8; j++) acc[i][j] = 0.f;

    const int arow = tid >> 1, ak = (tid & 1) * 4;
    const int bkr = tid >> 5, bnc = (tid & 31) * 4;

    for (int k0 = 0; k0 < Klen; k0 += 8) {
        float4 av = *(const float4*)(A + (size_t)(bm + arow) * lda + k0 + ak);
        As[ak + 0][arow] = av.x; As[ak + 1][arow] = av.y;
        As[ak + 2][arow] = av.z; As[ak + 3][arow] = av.w;
        float4 bv = *(const float4*)(B + (size_t)(k0 + bkr) * ldb + bn + bnc);
        *(float4*)&Bs[bkr][bnc] = bv;
        __syncthreads();
#pragma unroll
        for (int kk = 0; kk < 8; kk++) {
            float a[8], b[8];
            *(float4*)&a[0] = *(const float4*)&As[kk][ty * 8];
            *(float4*)&a[4] = *(const float4*)&As[kk][ty * 8 + 4];
            *(float4*)&b[0] = *(const float4*)&Bs[kk][tx * 8];
            *(float4*)&b[4] = *(const float4*)&Bs[kk][tx * 8 + 4];
#pragma unroll
            for (int i = 0; i < 8; i++)
#pragma unroll
                for (int j = 0; j < 8; j++) acc[i][j] = fmaf(a[i], b[j], acc[i][j]);
        }
        __syncthreads();
    }
#pragma unroll
    for (int i = 0; i < 8; i++) {
        int row = bm + ty * 8 + i;
#pragma unroll
        for (int j = 0; j < 8; j += 4) {
            int col = bn + tx * 8 + j;
            *(float4*)(C + (size_t)row * ldc + col) = *(float4*)&acc[i][j];
        }
    }
}

// Merged Weff + Wfinal partials in ONE launch.
__global__ void __launch_bounds__(256)
weights_part_kernel(const float* __restrict__ W_in, const float* __restrict__ Wq,
                    const float* __restrict__ Wk, const float* __restrict__ Wv,
                    const float* __restrict__ Wout, const float* __restrict__ Wo) {
    int z = blockIdx.z;
    if (z < 12) {
        int t = z >> 2, sl = z & 3;
        const float* Bt = (t == 0) ? Wq : (t == 1 ? Wk : Wv);
        const float* A = W_in + (size_t)t * HIDDEN_DIM * HIDDEN_DIM + sl * 128;
        const float* B = Bt + (size_t)sl * 128 * INPUT_DIM;
        float* C = g_WeffPart + (size_t)sl * QKV_DIM * INPUT_DIM +
                   (size_t)t * HIDDEN_DIM * INPUT_DIM;
        sgemm_tile_nn(128, HIDDEN_DIM, INPUT_DIM, INPUT_DIM, A, B, C,
                      blockIdx.y * 128, blockIdx.x * 128);
    } else {
        if (blockIdx.x >= HIDDEN_DIM / 128 || blockIdx.y >= OUTPUT_DIM / 128) return;
        int sl = z - 12;
        sgemm_tile_nn(128, HIDDEN_DIM, HIDDEN_DIM, HIDDEN_DIM,
                      Wout + sl * 128, Wo + (size_t)sl * 128 * HIDDEN_DIM,
                      g_WfinalPart + (size_t)sl * OUTPUT_DIM * HIDDEN_DIM,
                      blockIdx.y * 128, blockIdx.x * 128);
    }
}

// ---------------------------------------------------------------------------
// Merged reduction: Weff partials -> fp16 B; Wfinal partials -> fp16
// ---------------------------------------------------------------------------
#define N_WEFF4  ((size_t)QKV_DIM * INPUT_DIM / 4)     // 294912
#define N_WFIN4  ((size_t)OUTPUT_DIM * HIDDEN_DIM / 4) // 32768
__global__ void reduce_weights_kernel() {
    size_t i = (size_t)blockIdx.x * blockDim.x + threadIdx.x;
    if (i < N_WEFF4) {
        const size_t stride = (size_t)QKV_DIM * INPUT_DIM;
        float4 s = *(const float4*)(g_WeffPart + i * 4);
#pragma unroll
        for (int p = 1; p < SPLITK; p++) {
            float4 v = *(const float4*)(g_WeffPart + p * stride + i * 4);
            s.x += v.x; s.y += v.y; s.z += v.z; s.w += v.w;
        }
        uint2 h;
        h.x = packh2(s.x, s.y); h.y = packh2(s.z, s.w);
        *(uint2*)(g_Bhi + i * 4) = h;
    } else if (i < N_WEFF4 + N_WFIN4) {
        size_t j = i - N_WEFF4;
        const size_t stride = (size_t)OUTPUT_DIM * HIDDEN_DIM;
        float4 s = *(const float4*)(g_WfinalPart + j * 4);
#pragma unroll
        for (int p = 1; p < SPLITK; p++) {
            float4 v = *(const float4*)(g_WfinalPart + p * stride + j * 4);
            s.x += v.x; s.y += v.y; s.z += v.z; s.w += v.w;
        }
        uint2 h;
        h.x = packh2(s.x, s.y); h.y = packh2(s.z, s.w);
        *(uint2*)(g_Wfinalh + j * 4) = h;
    }
}

// ---------------------------------------------------------------------------
// chunk fp32 -> fp16 (rows >= NUM_CHUNKS zero-padded to M_PAD)
// ---------------------------------------------------------------------------
__global__ void convert_chunk_kernel(const float* __restrict__ x) {
    size_t i = (size_t)blockIdx.x * blockDim.x + threadIdx.x;
    const size_t n8 = (size_t)M_PAD * INPUT_DIM / 8;
    if (i >= n8) return;
    uint4 out = make_uint4(0, 0, 0, 0);
    if (i * 8 < (size_t)NUM_CHUNKS * INPUT_DIM) {
        float4 v0 = *(const float4*)(x + i * 8);
        float4 v1 = *(const float4*)(x + i * 8 + 4);
        out.x = packh2(v0.x, v0.y); out.y = packh2(v0.z, v0.w);
        out.z = packh2(v1.x, v1.y); out.w = packh2(v1.z, v1.w);
    }
    *(uint4*)(g_Ahi + i * 8) = out;
}

// ---------------------------------------------------------------------------
// QKV GEMM via mma.sync fp16 (R11-proven 8-warp config). fp16 out.
// ---------------------------------------------------------------------------
__global__ void __launch_bounds__(256, 2)
qkv_mma_kernel(const float* __restrict__ beff, __half* __restrict__ C) {
    extern __shared__ __align__(128) char smem[];
    const uint32_t sb = smem_u32(smem);
    const int tid = threadIdx.x, lane = tid & 31, wid = tid >> 5;
    const int bm = blockIdx.y * 128, bn = blockIdx.x * 128;
    const int wm = (wid & 1) * 64, wn = (wid >> 1) * 32;

    float c[4][4][4];
#pragma unroll
    for (int mt = 0; mt < 4; mt++)
#pragma unroll
        for (int nt = 0; nt < 4; nt++)
#pragma unroll
            for (int r = 0; r < 4; r++) c[mt][nt][r] = 0.f;

    const uint32_t sw   = (uint32_t)((lane & 7) << 4);
    const int arow = wm + (lane & 15);
    const uint32_t ahi  = (uint32_t)(((lane >> 4) & 1) * 16);
    const int brow = wn + (lane & 7) + ((lane >> 4) & 1) * 8;
    const uint32_t bhi  = (uint32_t)(((lane >> 3) & 1) * 16);

    auto issue = [&](int chunk) {
        int st = chunk % 3;
        int ko = chunk * CHUNK_K;
        uint32_t base = sb + st * STAGE_B;
#pragma unroll
        for (int i = 0; i < 8; i++) {
            int u = tid + 256 * i;
            int row = (u >> 3) & 127;
            int c16 = u & 7;
            bool isB = u >= 1024;
            uint32_t dst = base + (isB ? TILE_BYTES : 0) + row * 128 +
                           ((uint32_t)(c16 * 16) ^ (uint32_t)((row & 7) << 4));
            const __half* src =
                isB ? g_Bhi + (size_t)(bn + row) * INPUT_DIM + ko + c16 * 8
                    : g_Ahi + (size_t)(bm + row) * INPUT_DIM + ko + c16 * 8;
            cp16(dst, src);
        }
        cp_commit();
    };

    issue(0);
    issue(1);

    for (int i = 0; i < NCHUNKS; i++) {
        cp_wait<1>();
        __syncthreads();
        if (i + 2 < NCHUNKS) issue(i + 2);
        else cp_commit();
        uint32_t sa = sb + (i % 3) * STAGE_B;
        uint32_t sB = sa + TILE_BYTES;
#pragma unroll
        for (int kf = 0; kf < 4; kf++) {
            uint32_t a[4][4], b[2][4];
#pragma unroll
            for (int mt = 0; mt < 4; mt++)
                ldsm4(a[mt][0], a[mt][1], a[mt][2], a[mt][3],
                      sa + (uint32_t)(arow + mt * 16) * 128 +
                          (((uint32_t)(kf * 32) + ahi) ^ sw));
#pragma unroll
            for (int bt = 0; bt < 2; bt++)
                ldsm4(b[bt][0], b[bt][1], b[bt][2], b[bt][3],
                      sB + (uint32_t)(brow + bt * 16) * 128 +
                          (((uint32_t)(kf * 32) + bhi) ^ sw));
#pragma unroll
            for (int mt = 0; mt < 4; mt++)
#pragma unroll
                for (int nt = 0; nt < 4; nt++)
                    mma16816(c[mt][nt], a[mt][0], a[mt][1], a[mt][2], a[mt][3],
                             b[nt >> 1][(nt & 1) * 2], b[nt >> 1][(nt & 1) * 2 + 1]);
        }
    }

    const int rr = bm + wm + (lane >> 2);
    const int cc = bn + wn + (lane & 3) * 2;
#pragma unroll
    for (int mt = 0; mt < 4; mt++) {
#pragma unroll
        for (int nt = 0; nt < 4; nt++) {
            int col = cc + nt * 8;
            float b0 = beff[col], b1 = beff[col + 1];
            int row = rr + mt * 16;
            if (row < NUM_CHUNKS) {
                uint32_t v = packh2(c[mt][nt][0] + b0, c[mt][nt][1] + b1);
                *(uint32_t*)(C + (size_t)row * QKV_DIM + col) = v;
            }
            if (row + 8 < NUM_CHUNKS) {
                uint32_t v = packh2(c[mt][nt][2] + b0, c[mt][nt][3] + b1);
                *(uint32_t*)(C + (size_t)(row + 8) * QKV_DIM + col) = v;
            }
        }
    }
}

// ---------------------------------------------------------------------------
// Final projection via mma.sync fp16 (R12-proven):
// out[2048,256] = pooled[2048,512](fp16) @ Wfinalh[256,512]^T + bfinal
// ---------------------------------------------------------------------------
__global__ void __launch_bounds__(256, 2)
out_mma_kernel(const float* __restrict__ bfinal, float* __restrict__ C) {
    extern __shared__ __align__(128) char smem[];
    const uint32_t sb = smem_u32(smem);
    const int tid = threadIdx.x, lane = tid & 31, wid = tid >> 5;
    const int bm = blockIdx.y * 128, bn = blockIdx.x * 128;
    const int wm = (wid & 1) * 64, wn = (wid >> 1) * 32;

    float c[4][4][4];
#pragma unroll
    for (int mt = 0; mt < 4; mt++)
#pragma unroll
        for (int nt = 0; nt < 4; nt++)
#pragma unroll
            for (int r = 0; r < 4; r++) c[mt][nt][r] = 0.f;

    const uint32_t sw   = (uint32_t)((lane & 7) << 4);
    const int arow = wm + (lane & 15);
    const uint32_t ahi  = (uint32_t)(((lane >> 4) & 1) * 16);
    const int brow = wn + (lane & 7) + ((lane >> 4) & 1) * 8;
    const uint32_t bhi  = (uint32_t)(((lane >> 3) & 1) * 16);

    auto issue = [&](int chunk) {
        int st = chunk % 3;
        int ko = chunk * CHUNK_K;
        uint32_t base = sb + st * STAGE_B;
#pragma unroll
        for (int i = 0; i < 8; i++) {
            int u = tid + 256 * i;
            int row = (u >> 3) & 127;
            int c16 = u & 7;
            bool isB = u >= 1024;
            uint32_t dst = base + (isB ? TILE_BYTES : 0) + row * 128 +
                           ((uint32_t)(c16 * 16) ^ (uint32_t)((row & 7) << 4));
            const __half* src =
                isB ? g_Wfinalh + (size_t)(bn + row) * HIDDEN_DIM + ko + c16 * 8
                    : g_pooled + (size_t)(bm + row) * HIDDEN_DIM + ko + c16 * 8;
            cp16(dst, src);
        }
        cp_commit();
    };

    issue(0);
    issue(1);

    for (int i = 0; i < NCHUNKS_O; i++) {
        cp_wait<1>();
        __syncthreads();
        if (i + 2 < NCHUNKS_O) issue(i + 2);
        else cp_commit();
        uint32_t sa = sb + (i % 3) * STAGE_B;
        uint32_t sB = sa + TILE_BYTES;
#pragma unroll
        for (int kf = 0; kf < 4; kf++) {
            uint32_t a[4][4], b[2][4];
#pragma unroll
            for (int mt = 0; mt < 4; mt++)
                ldsm4(a[mt][0], a[mt][1], a[mt][2], a[mt][3],
                      sa + (uint32_t)(arow + mt * 16) * 128 +
                          (((uint32_t)(kf * 32) + ahi) ^ sw));
#pragma unroll
            for (int bt = 0; bt < 2; bt++)
                ldsm4(b[bt][0], b[bt][1], b[bt][2], b[bt][3],
                      sB + (uint32_t)(brow + bt * 16) * 128 +
                          (((uint32_t)(kf * 32) + bhi) ^ sw));
#pragma unroll
            for (int mt = 0; mt < 4; mt++)
#pragma unroll
                for (int nt = 0; nt < 4; nt++)
                    mma16816(c[mt][nt], a[mt][0], a[mt][1], a[mt][2], a[mt][3],
                             b[nt >> 1][(nt & 1) * 2], b[nt >> 1][(nt & 1) * 2 + 1]);
        }
    }

    const int rr = bm + wm + (lane >> 2);
    const int cc = bn + wn + (lane & 3) * 2;
#pragma unroll
    for (int mt = 0; mt < 4; mt++) {
#pragma unroll
        for (int nt = 0; nt < 4; nt++) {
            int col = cc + nt * 8;
            float b0 = bfinal[col], b1 = bfinal[col + 1];
            int row = rr + mt * 16;
            float2 v0 = make_float2(c[mt][nt][0] + b0, c[mt][nt][1] + b1);
            *(float2*)(C + (size_t)row * OUTPUT_DIM + col) = v0;
            float2 v1 = make_float2(c[mt][nt][2] + b0, c[mt][nt][3] + b1);
            *(float2*)(C + (size_t)(row + 8) * OUTPUT_DIM + col) = v1;
        }
    }
}

// ---------------------------------------------------------------------------
// Attention + masked mean pool: TWO heads per block, 8 warps all active.
// Block = (cell, head-pair p). Heads h0 = 2p, h1 = 2p+1.
// smem: Q0,K0,Q1,K1 (4 x 8192 swizzled) | ps0,ps1 (2 x 64x68 f32) | wsum(2x64)
//       | part(2x2x64) | ridx(64)
// ---------------------------------------------------------------------------
#define A2_QK    0                       // 32768: [mat=Q0,K0,Q1,K1] x 8192
#define A2_PS    32768                   // 2 x 17408 = 34816
#define A2_WS    67584                   // 2*64*4 = 512
#define A2_PART  68096                   // 2*2*64*4 = 1024
#define A2_RIDX  69120                   // 64*4
#define A2_TOTAL 69376

__global__ void __launch_bounds__(256)
attn_pool_kernel(const __half* __restrict__ QKV, const void* __restrict__ cell_idx,
                 const void* __restrict__ cell_len, __half* __restrict__ pooled) {
    extern __shared__ __align__(128) char sm2[];
    const uint32_t sb = smem_u32(sm2);
    float* ps   = (float*)(sm2 + A2_PS);     // [2][64][68]
    float* wsum = (float*)(sm2 + A2_WS);     // [2][64]
    float* part = (float*)(sm2 + A2_PART);   // [2][2][64]
    int*   ridx = (int*)(sm2 + A2_RIDX);

    const int c = blockIdx.x, pr = blockIdx.y, tid = threadIdx.x;
    const int lane = tid & 31, wid = tid >> 5;
    const int sI = g_idx_is64 ? 2 : 1;
    const int sL = g_len_is64 ? 2 : 1;
    const int* idx32 = (const int*)cell_idx;
    const int* len32 = (const int*)cell_len;

    int len = len32[(size_t)c * sL];
    int Leff = len < 1 ? 1 : (len > 64 ? 64 : len);
    if (tid < 64) ridx[tid] = idx32[((size_t)c * MAX_LEN + tid) * sI];
    __syncthreads();

    // Phase 1: gather Q,K for BOTH heads via cp.async.
    // 2048 16B units: mat = u>>9 in {Q0,K0,Q1,K1}; 8 units/thread.
#pragma unroll
    for (int it = 0; it < 8; it++) {
        int u = tid + 256 * it;
        int mat = u >> 9;
        int idx = u & 511;
        int row = idx >> 3, c16 = idx & 7;
        uint32_t dst = sb + A2_QK + mat * 8192 + row * 128 +
                       ((uint32_t)(c16 * 16) ^ (uint32_t)((row & 7) << 4));
        if (row < Leff) {
            int hoff = (2 * pr + (mat >> 1)) * HEAD_DIM + (mat & 1) * HIDDEN_DIM;
            const __half* src = QKV + (size_t)ridx[row] * QKV_DIM + hoff + c16 * 8;
            cp16(dst, src);
        } else {
            asm volatile("st.shared.v4.b32 [%0], {%1,%1,%1,%1};"
                         :: "r"(dst), "r"(0u) : "memory");
        }
    }
    cp_commit();
    cp_wait<0>();
    __syncthreads();

    // Phase 2: warp w -> head hw = w>>2, warp-in-head ww = w&3 computes
    // score rows [16ww, 16ww+16) via mma + softmax -> ps[hw].
    {
        const int hw = wid >> 2, ww = wid & 3;
        float* psh = ps + hw * (64 * 68);
        const uint32_t sq = sb + A2_QK + hw * 16384;
        const uint32_t sk = sq + 8192;

        float cfr[8][4];
#pragma unroll
        for (int nt = 0; nt < 8; nt++)
#pragma unroll
            for (int r = 0; r < 4; r++) cfr[nt][r] = 0.f;

        const uint32_t swl = (uint32_t)((lane & 7) << 4);
        const uint32_t abase = sq + (uint32_t)(16 * ww + (lane & 15)) * 128;
        const uint32_t ahi = (uint32_t)(((lane >> 4) & 1) * 16);
        const int brow = (lane & 7) + ((lane >> 4) & 1) * 8;
        const uint32_t bhi = (uint32_t)(((lane >> 3) & 1) * 16);

#pragma unroll
        for (int kf = 0; kf < 4; kf++) {
            uint32_t a0, a1, a2, a3, b[4][4];
            ldsm4(a0, a1, a2, a3, abase + (((uint32_t)(kf * 32) + ahi) ^ swl));
#pragma unroll
            for (int bt = 0; bt < 4; bt++)
                ldsm4(b[bt][0], b[bt][1], b[bt][2], b[bt][3],
                      sk + (uint32_t)(bt * 16 + brow) * 128 +
                          (((uint32_t)(kf * 32) + bhi) ^ swl));
#pragma unroll
            for (int nt = 0; nt < 8; nt++)
                mma16816(cfr[nt], a0, a1, a2, a3,
                         b[nt >> 1][(nt & 1) * 2], b[nt >> 1][(nt & 1) * 2 + 1]);
        }

        float m0 = -1e30f, m1 = -1e30f;
#pragma unroll
        for (int nt = 0; nt < 8; nt++)
#pragma unroll
            for (int rg = 0; rg < 2; rg++) {
                int col = nt * 8 + (lane & 3) * 2 + rg;
                if (col < Leff) {
                    m0 = fmaxf(m0, cfr[nt][rg] * 0.125f);
                    m1 = fmaxf(m1, cfr[nt][2 + rg] * 0.125f);
                }
            }
        m0 = fmaxf(m0, __shfl_xor_sync(0xffffffffu, m0, 1));
        m0 = fmaxf(m0, __shfl_xor_sync(0xffffffffu, m0, 2));
        m1 = fmaxf(m1, __shfl_xor_sync(0xffffffffu, m1, 1));
        m1 = fmaxf(m1, __shfl_xor_sync(0xffffffffu, m1, 2));

        float s0 = 0.f, s1 = 0.f;
#pragma unroll
        for (int nt = 0; nt < 8; nt++)
#pragma unroll
            for (int rg = 0; rg < 2; rg++) {
                int col = nt * 8 + (lane & 3) * 2 + rg;
                float e0 = (col < Leff) ? __expf(cfr[nt][rg] * 0.125f - m0) : 0.f;
                float e1 = (col < Leff) ? __expf(cfr[nt][2 + rg] * 0.125f - m1) : 0.f;
                cfr[nt][rg] = e0;
                cfr[nt][2 + rg] = e1;
                s0 += e0; s1 += e1;
            }
        s0 += __shfl_xor_sync(0xffffffffu, s0, 1);
        s0 += __shfl_xor_sync(0xffffffffu, s0, 2);
        s1 += __shfl_xor_sync(0xffffffffu, s1, 1);
        s1 += __shfl_xor_sync(0xffffffffu, s1, 2);
        float i0 = 1.f / s0, i1 = 1.f / s1;

        int row0 = 16 * ww + (lane >> 2);
#pragma unroll
        for (int nt = 0; nt < 8; nt++)
#pragma unroll
            for (int rg = 0; rg < 2; rg++) {
                int col = nt * 8 + (lane & 3) * 2 + rg;
                psh[row0 * 68 + col] = cfr[nt][rg] * i0;
                psh[(row0 + 8) * 68 + col] = cfr[nt][2 + rg] * i1;
            }
    }
    __syncthreads();

    // Phase 3: column mean over valid query rows (128 threads: 2 heads x 64)
    if (tid < 128) {
        int hd = tid >> 6, col = tid & 63;
        const float* psh = ps + hd * (64 * 68);
        float s = 0.f;
        for (int ll = 0; ll < Leff; ll++) s += psh[ll * 68 + col];
        wsum[hd * 64 + col] = s / (float)Leff;
    }
    __syncthreads();

    // Phase 4: pooled[d] = sum_m wsum[m] * V[m][d], 2 heads x 2 partitions x 64
    {
        int hd = tid >> 7, pt = (tid >> 6) & 1, d = tid & 63;
        int hoff = (2 * pr + hd) * HEAD_DIM;
        float acc = 0.f;
        for (int m = pt; m < Leff; m += 2)
            acc = fmaf(wsum[hd * 64 + m],
                       __half2float(QKV[(size_t)ridx[m] * QKV_DIM + 2 * HIDDEN_DIM + hoff + d]),
                       acc);
        part[(hd * 2 + pt) * 64 + d] = acc;
    }
    __syncthreads();
    if (tid < 128) {
        int hd = tid >> 6, d = tid & 63;
        pooled[(size_t)c * HIDDEN_DIM + (2 * pr + hd) * HEAD_DIM + d] =
            __float2half(part[(hd * 2) * 64 + d] + part[(hd * 2 + 1) * 64 + d]);
    }
}

// ---------------------------------------------------------------------------
// Launch (with stream-forked convert: runs concurrent with weights chain)
// ---------------------------------------------------------------------------
extern "C" void kernel_launch(void* const* d_in, const int* in_sizes, int n_in,
                              void* d_out, int out_size) {
    const float* chunk = (const float*)d_in[0];
    const float* Wq   = (const float*)d_in[1];
    const float* bq   = (const float*)d_in[2];
    const float* Wk   = (const float*)d_in[3];
    const float* bk   = (const float*)d_in[4];
    const float* Wv   = (const float*)d_in[5];
    const float* bv   = (const float*)d_in[6];
    const float* W_in = (const float*)d_in[7];
    const float* b_in = (const float*)d_in[8];
    const float* Wo   = (const float*)d_in[9];
    const float* bo   = (const float*)d_in[10];
    const float* Wout = (const float*)d_in[11];
    const float* bout = (const float*)d_in[12];
    const void*  cidx = d_in[13];
    const void*  clen = d_in[14];
    float* out = (float*)d_out;

    __half *pQKV, *pPooled;
    float *pbeff, *pbfinal;
    cudaGetSymbolAddress((void**)&pQKV, g_QKV);
    cudaGetSymbolAddress((void**)&pPooled, g_pooled);
    cudaGetSymbolAddress((void**)&pbeff, g_beff);
    cudaGetSymbolAddress((void**)&pbfinal, g_bfinal);

    static cudaStream_t s2 = nullptr;
    static cudaEvent_t evFork = nullptr, evJoin = nullptr;
    static bool attr_set = false;
    if (!attr_set) {
        cudaFuncSetAttribute(qkv_mma_kernel, cudaFuncAttributeMaxDynamicSharedMemorySize,
                             SMEM_MMA);
        cudaFuncSetAttribute(out_mma_kernel, cudaFuncAttributeMaxDynamicSharedMemorySize,
                             SMEM_MMA);
        cudaFuncSetAttribute(attn_pool_kernel, cudaFuncAttributeMaxDynamicSharedMemorySize,
                             A2_TOTAL);
        cudaStreamCreateWithFlags(&s2, cudaStreamNonBlocking);
        cudaEventCreateWithFlags(&evFork, cudaEventDisableTiming);
        cudaEventCreateWithFlags(&evJoin, cudaEventDisableTiming);
        attr_set = true;
    }

    // fork: convert on side stream, concurrent with setup + weights chain
    cudaEventRecord(evFork, 0);
    cudaStreamWaitEvent(s2, evFork, 0);
    convert_chunk_kernel<<<((size_t)M_PAD * INPUT_DIM / 8 + 255) / 256, 256, 0, s2>>>(chunk);
    cudaEventRecord(evJoin, s2);

    // main stream: setup + merged small GEMMs + reduce
    setup_kernel<<<(QKV_DIM + OUTPUT_DIM + 1 + 255) / 256, 256>>>(
        (const int*)cidx, (const int*)clen,
        W_in, b_in, bq, bk, bv, Wout, bo, bout, pbeff, pbfinal);
    weights_part_kernel<<<dim3(INPUT_DIM / 128, HIDDEN_DIM / 128, 16), 256>>>(
        W_in, Wq, Wk, Wv, Wout, Wo);
    reduce_weights_kernel<<<(unsigned)((N_WEFF4 + N_WFIN4 + 255) / 256), 256>>>();

    // join: qkv needs both Ahi (side stream) and Bhi (main stream)
    cudaStreamWaitEvent(0, evJoin, 0);

    // QKV projection (8-warp R11 config)
    qkv_mma_kernel<<<dim3(QKV_DIM / 128, M_PAD / 128), 256, SMEM_MMA>>>(pbeff, pQKV);

    // fused attention + masked mean pool (2 heads per block, 8 warps active)
    attn_pool_kernel<<<dim3(NUM_CELLS, NUM_HEADS / 2), 256, A2_TOTAL>>>(
        pQKV, cidx, clen, pPooled);

    // final projection via mma
    out_mma_kernel<<<dim3(OUTPUT_DIM / 128, NUM_CELLS / 128), 256, SMEM_MMA>>>(pbfinal, out);
}

// round 14
// speedup vs baseline: 1.0688x; 1.0688x over previous
#include <cuda_runtime.h>
#include <cuda_fp16.h>
#include <cuda_bf16.h>
#include <math.h>
#include <stdint.h>

// ---------------------------------------------------------------------------
// Problem constants
// ---------------------------------------------------------------------------
#define NUM_HEADS   8
#define NUM_CHUNKS  50000
#define INPUT_DIM   768
#define HIDDEN_DIM  512
#define OUTPUT_DIM  256
#define NUM_CELLS   2048
#define MAX_LEN     64
#define HEAD_DIM    64
#define QKV_DIM     1536
#define M_PAD       50048              // 391 * 128
#define SPLITK      4

// mma GEMM geometry (k-chunk 64, swizzled smem, 3 stages, 2 CTA/SM)
#define CHUNK_K     64
#define NCHUNKS     12                 // single fp16 pass: 768/64
#define NCHUNKS_O   8                  // final projection: 512/64
#define TILE_BYTES  (128 * 128)        // 16384 (128 rows x 128B swizzled)
#define STAGE_B     (2 * TILE_BYTES)   // 32768
#define SMEM_MMA    (3 * STAGE_B)      // 98304

// ---------------------------------------------------------------------------
// Device-global scratch (allocation-free contract)
// ---------------------------------------------------------------------------
__device__ __align__(1024) __half g_Ahi[(size_t)M_PAD * INPUT_DIM];
__device__ __align__(1024) __half g_Bhi[QKV_DIM * INPUT_DIM];
__device__ __align__(1024) __half g_QKV[(size_t)NUM_CHUNKS * QKV_DIM];
__device__ __align__(1024) __half g_pooled[NUM_CELLS * HIDDEN_DIM];
__device__ __align__(1024) __half g_Wfinalh[OUTPUT_DIM * HIDDEN_DIM];
__device__ __align__(256) float g_beff[QKV_DIM];
__device__ __align__(256) float g_bfinal[OUTPUT_DIM];
__device__ __align__(256) float g_WeffPart[SPLITK * QKV_DIM * INPUT_DIM];
__device__ __align__(256) float g_WfinalPart[SPLITK * OUTPUT_DIM * HIDDEN_DIM];
__device__ int g_idx_is64;
__device__ int g_len_is64;

// ---------------------------------------------------------------------------
// PTX helpers (plain-sm_80-level: safe for non-'a' ptx target)
// ---------------------------------------------------------------------------
__device__ __forceinline__ uint32_t smem_u32(const void* p) {
    uint32_t a;
    asm("{ .reg .u64 t; cvta.to.shared.u64 t, %1; cvt.u32.u64 %0, t; }"
        : "=r"(a) : "l"(p));
    return a;
}
__device__ __forceinline__ void cp16(uint32_t d, const void* s) {
    asm volatile("cp.async.cg.shared.global [%0], [%1], 16;" :: "r"(d), "l"(s));
}
__device__ __forceinline__ void cp_commit() {
    asm volatile("cp.async.commit_group;" ::: "memory");
}
template <int N>
__device__ __forceinline__ void cp_wait() {
    asm volatile("cp.async.wait_group %0;" :: "n"(N) : "memory");
}
__device__ __forceinline__ void ldsm4(uint32_t& r0, uint32_t& r1, uint32_t& r2,
                                      uint32_t& r3, uint32_t a) {
    asm volatile("ldmatrix.sync.aligned.m8n8.x4.shared.b16 {%0,%1,%2,%3}, [%4];"
                 : "=r"(r0), "=r"(r1), "=r"(r2), "=r"(r3) : "r"(a));
}
__device__ __forceinline__ void mma16816(float* c, uint32_t a0, uint32_t a1,
                                         uint32_t a2, uint32_t a3,
                                         uint32_t b0, uint32_t b1) {
    asm volatile("mma.sync.aligned.m16n8k16.row.col.f32.f16.f16.f32 "
                 "{%0,%1,%2,%3}, {%4,%5,%6,%7}, {%8,%9}, {%0,%1,%2,%3};"
                 : "+f"(c[0]), "+f"(c[1]), "+f"(c[2]), "+f"(c[3])
                 : "r"(a0), "r"(a1), "r"(a2), "r"(a3), "r"(b0), "r"(b1));
}
__device__ __forceinline__ uint32_t packh2(float a, float b) {
    __half2 h = __floats2half2_rn(a, b);
    return *(uint32_t*)&h;
}

// ---------------------------------------------------------------------------
// dtype detection + combined biases (merged, one launch)
// ---------------------------------------------------------------------------
__global__ void setup_kernel(const int* __restrict__ iw, const int* __restrict__ lw,
                             const float* __restrict__ W_in, const float* __restrict__ b_in,
                             const float* __restrict__ bq, const float* __restrict__ bk,
                             const float* __restrict__ bv, const float* __restrict__ Wout,
                             const float* __restrict__ bo, const float* __restrict__ bout,
                             float* __restrict__ beff, float* __restrict__ bfinal) {
    int i = blockIdx.x * blockDim.x + threadIdx.x;
    if (i == QKV_DIM + OUTPUT_DIM) {
        int oi = 0, ol = 0;
        for (int k = 0; k < 256; k++) oi |= iw[2 * k + 1];
        for (int k = 0; k < 256; k++) ol |= lw[2 * k + 1];
        g_idx_is64 = (oi == 0) ? 1 : 0;
        g_len_is64 = (ol == 0) ? 1 : 0;
        return;
    }
    if (i < QKV_DIM) {
        const float* bs = (i < HIDDEN_DIM) ? bq : (i < 2 * HIDDEN_DIM ? bk : bv);
        const float* w = W_in + (size_t)i * HIDDEN_DIM;
        float s = 0.f;
        for (int k = 0; k < HIDDEN_DIM; k++) s = fmaf(w[k], bs[k], s);
        beff[i] = s + b_in[i];
    } else if (i < QKV_DIM + OUTPUT_DIM) {
        int o = i - QKV_DIM;
        const float* w = Wout + (size_t)o * HIDDEN_DIM;
        float s = 0.f;
        for (int k = 0; k < HIDDEN_DIM; k++) s = fmaf(w[k], bo[k], s);
        bfinal[o] = s + bout[o];
    }
}

// ---------------------------------------------------------------------------
// SIMT tile GEMM body (128x128, 8x8/thread). Small split-K GEMMs.
// ---------------------------------------------------------------------------
__device__ __forceinline__ void sgemm_tile_nn(int Klen, int lda, int ldb, int ldc,
                                              const float* __restrict__ A,
                                              const float* __restrict__ B,
                                              float* __restrict__ C, int bm, int bn) {
    __shared__ float As[8][128];
    __shared__ float Bs[8][128];
    const int tid = threadIdx.x;
    const int tx = tid & 15, ty = tid >> 4;
    float acc[8][8];
#pragma unroll
    for (int i = 0; i < 8; i++)
#pragma unroll
        for (int j = 0; j < 8; j++) acc[i][j] = 0.f;

    const int arow = tid >> 1, ak = (tid & 1) * 4;
    const int bkr = tid >> 5, bnc = (tid & 31) * 4;

    for (int k0 = 0; k0 < Klen; k0 += 8) {
        float4 av = *(const float4*)(A + (size_t)(bm + arow) * lda + k0 + ak);
        As[ak + 0][arow] = av.x; As[ak + 1][arow] = av.y;
        As[ak + 2][arow] = av.z; As[ak + 3][arow] = av.w;
        float4 bv = *(const float4*)(B + (size_t)(k0 + bkr) * ldb + bn + bnc);
        *(float4*)&Bs[bkr][bnc] = bv;
        __syncthreads();
#pragma unroll
        for (int kk = 0; kk < 8; kk++) {
            float a[8], b[8];
            *(float4*)&a[0] = *(const float4*)&As[kk][ty * 8];
            *(float4*)&a[4] = *(const float4*)&As[kk][ty * 8 + 4];
            *(float4*)&b[0] = *(const float4*)&Bs[kk][tx * 8];
            *(float4*)&b[4] = *(const float4*)&Bs[kk][tx * 8 + 4];
#pragma unroll
            for (int i = 0; i < 8; i++)
#pragma unroll
                for (int j = 0; j < 8; j++) acc[i][j] = fmaf(a[i], b[j], acc[i][j]);
        }
        __syncthreads();
    }
#pragma unroll
    for (int i = 0; i < 8; i++) {
        int row = bm + ty * 8 + i;
#pragma unroll
        for (int j = 0; j < 8; j += 4) {
            int col = bn + tx * 8 + j;
            *(float4*)(C + (size_t)row * ldc + col) = *(float4*)&acc[i][j];
        }
    }
}

// Merged Weff + Wfinal partials in ONE launch.
__global__ void __launch_bounds__(256)
weights_part_kernel(const float* __restrict__ W_in, const float* __restrict__ Wq,
                    const float* __restrict__ Wk, const float* __restrict__ Wv,
                    const float* __restrict__ Wout, const float* __restrict__ Wo) {
    int z = blockIdx.z;
    if (z < 12) {
        int t = z >> 2, sl = z & 3;
        const float* Bt = (t == 0) ? Wq : (t == 1 ? Wk : Wv);
        const float* A = W_in + (size_t)t * HIDDEN_DIM * HIDDEN_DIM + sl * 128;
        const float* B = Bt + (size_t)sl * 128 * INPUT_DIM;
        float* C = g_WeffPart + (size_t)sl * QKV_DIM * INPUT_DIM +
                   (size_t)t * HIDDEN_DIM * INPUT_DIM;
        sgemm_tile_nn(128, HIDDEN_DIM, INPUT_DIM, INPUT_DIM, A, B, C,
                      blockIdx.y * 128, blockIdx.x * 128);
    } else {
        if (blockIdx.x >= HIDDEN_DIM / 128 || blockIdx.y >= OUTPUT_DIM / 128) return;
        int sl = z - 12;
        sgemm_tile_nn(128, HIDDEN_DIM, HIDDEN_DIM, HIDDEN_DIM,
                      Wout + sl * 128, Wo + (size_t)sl * 128 * HIDDEN_DIM,
                      g_WfinalPart + (size_t)sl * OUTPUT_DIM * HIDDEN_DIM,
                      blockIdx.y * 128, blockIdx.x * 128);
    }
}

// ---------------------------------------------------------------------------
// Merged reduction: Weff partials -> fp16 B; Wfinal partials -> fp16
// ---------------------------------------------------------------------------
#define N_WEFF4  ((size_t)QKV_DIM * INPUT_DIM / 4)     // 294912
#define N_WFIN4  ((size_t)OUTPUT_DIM * HIDDEN_DIM / 4) // 32768
__global__ void reduce_weights_kernel() {
    size_t i = (size_t)blockIdx.x * blockDim.x + threadIdx.x;
    if (i < N_WEFF4) {
        const size_t stride = (size_t)QKV_DIM * INPUT_DIM;
        float4 s = *(const float4*)(g_WeffPart + i * 4);
#pragma unroll
        for (int p = 1; p < SPLITK; p++) {
            float4 v = *(const float4*)(g_WeffPart + p * stride + i * 4);
            s.x += v.x; s.y += v.y; s.z += v.z; s.w += v.w;
        }
        uint2 h;
        h.x = packh2(s.x, s.y); h.y = packh2(s.z, s.w);
        *(uint2*)(g_Bhi + i * 4) = h;
    } else if (i < N_WEFF4 + N_WFIN4) {
        size_t j = i - N_WEFF4;
        const size_t stride = (size_t)OUTPUT_DIM * HIDDEN_DIM;
        float4 s = *(const float4*)(g_WfinalPart + j * 4);
#pragma unroll
        for (int p = 1; p < SPLITK; p++) {
            float4 v = *(const float4*)(g_WfinalPart + p * stride + j * 4);
            s.x += v.x; s.y += v.y; s.z += v.z; s.w += v.w;
        }
        uint2 h;
        h.x = packh2(s.x, s.y); h.y = packh2(s.z, s.w);
        *(uint2*)(g_Wfinalh + j * 4) = h;
    }
}

// ---------------------------------------------------------------------------
// chunk fp32 -> fp16 (rows >= NUM_CHUNKS zero-padded to M_PAD)
// ---------------------------------------------------------------------------
__global__ void convert_chunk_kernel(const float* __restrict__ x) {
    size_t i = (size_t)blockIdx.x * blockDim.x + threadIdx.x;
    const size_t n8 = (size_t)M_PAD * INPUT_DIM / 8;
    if (i >= n8) return;
    uint4 out = make_uint4(0, 0, 0, 0);
    if (i * 8 < (size_t)NUM_CHUNKS * INPUT_DIM) {
        float4 v0 = *(const float4*)(x + i * 8);
        float4 v1 = *(const float4*)(x + i * 8 + 4);
        out.x = packh2(v0.x, v0.y); out.y = packh2(v0.z, v0.w);
        out.z = packh2(v1.x, v1.y); out.w = packh2(v1.z, v1.w);
    }
    *(uint4*)(g_Ahi + i * 8) = out;
}

// ---------------------------------------------------------------------------
// QKV GEMM via mma.sync fp16 (R11-proven 8-warp config). fp16 out.
// ---------------------------------------------------------------------------
__global__ void __launch_bounds__(256, 2)
qkv_mma_kernel(const float* __restrict__ beff, __half* __restrict__ C) {
    extern __shared__ __align__(128) char smem[];
    const uint32_t sb = smem_u32(smem);
    const int tid = threadIdx.x, lane = tid & 31, wid = tid >> 5;
    const int bm = blockIdx.y * 128, bn = blockIdx.x * 128;
    const int wm = (wid & 1) * 64, wn = (wid >> 1) * 32;

    float c[4][4][4];
#pragma unroll
    for (int mt = 0; mt < 4; mt++)
#pragma unroll
        for (int nt = 0; nt < 4; nt++)
#pragma unroll
            for (int r = 0; r < 4; r++) c[mt][nt][r] = 0.f;

    const uint32_t sw   = (uint32_t)((lane & 7) << 4);
    const int arow = wm + (lane & 15);
    const uint32_t ahi  = (uint32_t)(((lane >> 4) & 1) * 16);
    const int brow = wn + (lane & 7) + ((lane >> 4) & 1) * 8;
    const uint32_t bhi  = (uint32_t)(((lane >> 3) & 1) * 16);

    auto issue = [&](int chunk) {
        int st = chunk % 3;
        int ko = chunk * CHUNK_K;
        uint32_t base = sb + st * STAGE_B;
#pragma unroll
        for (int i = 0; i < 8; i++) {
            int u = tid + 256 * i;
            int row = (u >> 3) & 127;
            int c16 = u & 7;
            bool isB = u >= 1024;
            uint32_t dst = base + (isB ? TILE_BYTES : 0) + row * 128 +
                           ((uint32_t)(c16 * 16) ^ (uint32_t)((row & 7) << 4));
            const __half* src =
                isB ? g_Bhi + (size_t)(bn + row) * INPUT_DIM + ko + c16 * 8
                    : g_Ahi + (size_t)(bm + row) * INPUT_DIM + ko + c16 * 8;
            cp16(dst, src);
        }
        cp_commit();
    };

    issue(0);
    issue(1);

    for (int i = 0; i < NCHUNKS; i++) {
        cp_wait<1>();
        __syncthreads();
        if (i + 2 < NCHUNKS) issue(i + 2);
        else cp_commit();
        uint32_t sa = sb + (i % 3) * STAGE_B;
        uint32_t sB = sa + TILE_BYTES;
#pragma unroll
        for (int kf = 0; kf < 4; kf++) {
            uint32_t a[4][4], b[2][4];
#pragma unroll
            for (int mt = 0; mt < 4; mt++)
                ldsm4(a[mt][0], a[mt][1], a[mt][2], a[mt][3],
                      sa + (uint32_t)(arow + mt * 16) * 128 +
                          (((uint32_t)(kf * 32) + ahi) ^ sw));
#pragma unroll
            for (int bt = 0; bt < 2; bt++)
                ldsm4(b[bt][0], b[bt][1], b[bt][2], b[bt][3],
                      sB + (uint32_t)(brow + bt * 16) * 128 +
                          (((uint32_t)(kf * 32) + bhi) ^ sw));
#pragma unroll
            for (int mt = 0; mt < 4; mt++)
#pragma unroll
                for (int nt = 0; nt < 4; nt++)
                    mma16816(c[mt][nt], a[mt][0], a[mt][1], a[mt][2], a[mt][3],
                             b[nt >> 1][(nt & 1) * 2], b[nt >> 1][(nt & 1) * 2 + 1]);
        }
    }

    const int rr = bm + wm + (lane >> 2);
    const int cc = bn + wn + (lane & 3) * 2;
#pragma unroll
    for (int mt = 0; mt < 4; mt++) {
#pragma unroll
        for (int nt = 0; nt < 4; nt++) {
            int col = cc + nt * 8;
            float b0 = beff[col], b1 = beff[col + 1];
            int row = rr + mt * 16;
            if (row < NUM_CHUNKS) {
                uint32_t v = packh2(c[mt][nt][0] + b0, c[mt][nt][1] + b1);
                *(uint32_t*)(C + (size_t)row * QKV_DIM + col) = v;
            }
            if (row + 8 < NUM_CHUNKS) {
                uint32_t v = packh2(c[mt][nt][2] + b0, c[mt][nt][3] + b1);
                *(uint32_t*)(C + (size_t)(row + 8) * QKV_DIM + col) = v;
            }
        }
    }
}

// ---------------------------------------------------------------------------
// Final projection via mma.sync fp16 (R12-proven):
// out[2048,256] = pooled[2048,512](fp16) @ Wfinalh[256,512]^T + bfinal
// ---------------------------------------------------------------------------
__global__ void __launch_bounds__(256, 2)
out_mma_kernel(const float* __restrict__ bfinal, float* __restrict__ C) {
    extern __shared__ __align__(128) char smem[];
    const uint32_t sb = smem_u32(smem);
    const int tid = threadIdx.x, lane = tid & 31, wid = tid >> 5;
    const int bm = blockIdx.y * 128, bn = blockIdx.x * 128;
    const int wm = (wid & 1) * 64, wn = (wid >> 1) * 32;

    float c[4][4][4];
#pragma unroll
    for (int mt = 0; mt < 4; mt++)
#pragma unroll
        for (int nt = 0; nt < 4; nt++)
#pragma unroll
            for (int r = 0; r < 4; r++) c[mt][nt][r] = 0.f;

    const uint32_t sw   = (uint32_t)((lane & 7) << 4);
    const int arow = wm + (lane & 15);
    const uint32_t ahi  = (uint32_t)(((lane >> 4) & 1) * 16);
    const int brow = wn + (lane & 7) + ((lane >> 4) & 1) * 8;
    const uint32_t bhi  = (uint32_t)(((lane >> 3) & 1) * 16);

    auto issue = [&](int chunk) {
        int st = chunk % 3;
        int ko = chunk * CHUNK_K;
        uint32_t base = sb + st * STAGE_B;
#pragma unroll
        for (int i = 0; i < 8; i++) {
            int u = tid + 256 * i;
            int row = (u >> 3) & 127;
            int c16 = u & 7;
            bool isB = u >= 1024;
            uint32_t dst = base + (isB ? TILE_BYTES : 0) + row * 128 +
                           ((uint32_t)(c16 * 16) ^ (uint32_t)((row & 7) << 4));
            const __half* src =
                isB ? g_Wfinalh + (size_t)(bn + row) * HIDDEN_DIM + ko + c16 * 8
                    : g_pooled + (size_t)(bm + row) * HIDDEN_DIM + ko + c16 * 8;
            cp16(dst, src);
        }
        cp_commit();
    };

    issue(0);
    issue(1);

    for (int i = 0; i < NCHUNKS_O; i++) {
        cp_wait<1>();
        __syncthreads();
        if (i + 2 < NCHUNKS_O) issue(i + 2);
        else cp_commit();
        uint32_t sa = sb + (i % 3) * STAGE_B;
        uint32_t sB = sa + TILE_BYTES;
#pragma unroll
        for (int kf = 0; kf < 4; kf++) {
            uint32_t a[4][4], b[2][4];
#pragma unroll
            for (int mt = 0; mt < 4; mt++)
                ldsm4(a[mt][0], a[mt][1], a[mt][2], a[mt][3],
                      sa + (uint32_t)(arow + mt * 16) * 128 +
                          (((uint32_t)(kf * 32) + ahi) ^ sw));
#pragma unroll
            for (int bt = 0; bt < 2; bt++)
                ldsm4(b[bt][0], b[bt][1], b[bt][2], b[bt][3],
                      sB + (uint32_t)(brow + bt * 16) * 128 +
                          (((uint32_t)(kf * 32) + bhi) ^ sw));
#pragma unroll
            for (int mt = 0; mt < 4; mt++)
#pragma unroll
                for (int nt = 0; nt < 4; nt++)
                    mma16816(c[mt][nt], a[mt][0], a[mt][1], a[mt][2], a[mt][3],
                             b[nt >> 1][(nt & 1) * 2], b[nt >> 1][(nt & 1) * 2 + 1]);
        }
    }

    const int rr = bm + wm + (lane >> 2);
    const int cc = bn + wn + (lane & 3) * 2;
#pragma unroll
    for (int mt = 0; mt < 4; mt++) {
#pragma unroll
        for (int nt = 0; nt < 4; nt++) {
            int col = cc + nt * 8;
            float b0 = bfinal[col], b1 = bfinal[col + 1];
            int row = rr + mt * 16;
            float2 v0 = make_float2(c[mt][nt][0] + b0, c[mt][nt][1] + b1);
            *(float2*)(C + (size_t)row * OUTPUT_DIM + col) = v0;
            float2 v1 = make_float2(c[mt][nt][2] + b0, c[mt][nt][3] + b1);
            *(float2*)(C + (size_t)(row + 8) * OUTPUT_DIM + col) = v1;
        }
    }
}

// ---------------------------------------------------------------------------
// Attention + masked mean pool (R12-proven single-head, 35KB static smem)
// ---------------------------------------------------------------------------
#define AT_SQ    0        // 8192 bytes: Q fp16, 64 rows x 128B, swizzled
#define AT_SK    8192     // 8192 bytes: K fp16
#define AT_PS    16384    // 64*68*4 = 17408 bytes: probs (row stride 68 floats)
#define AT_WS    33792    // 64*4: wsum
#define AT_PART  34048    // 4*64*4: partial pooled
#define AT_RIDX  35072    // 64*4: gathered indices
#define AT_TOTAL 35328

__global__ void __launch_bounds__(256)
attn_pool_kernel(const __half* __restrict__ QKV, const void* __restrict__ cell_idx,
                 const void* __restrict__ cell_len, __half* __restrict__ pooled) {
    __shared__ __align__(128) char sm[AT_TOTAL];
    const uint32_t sb = smem_u32(sm);
    float* ps   = (float*)(sm + AT_PS);      // [64][68]
    float* wsum = (float*)(sm + AT_WS);
    float* part = (float*)(sm + AT_PART);    // [4][64]
    int*   ridx = (int*)(sm + AT_RIDX);

    const int c = blockIdx.x, h = blockIdx.y, tid = threadIdx.x;
    const int lane = tid & 31, wid = tid >> 5;
    const int hoff = h * HEAD_DIM;
    const int sI = g_idx_is64 ? 2 : 1;
    const int sL = g_len_is64 ? 2 : 1;
    const int* idx32 = (const int*)cell_idx;
    const int* len32 = (const int*)cell_len;

    int len = len32[(size_t)c * sL];
    int Leff = len < 1 ? 1 : (len > 64 ? 64 : len);
    if (tid < 64) ridx[tid] = idx32[((size_t)c * MAX_LEN + tid) * sI];
    __syncthreads();

    // Phase 1: gather Q,K fp16 via cp.async (zero rows >= Leff)
#pragma unroll
    for (int it = 0; it < 4; it++) {
        int u = tid + 256 * it;
        int mat = u >> 9;                  // 0 = Q, 1 = K
        int idx = u & 511;
        int row = idx >> 3, c16 = idx & 7;
        uint32_t dst = sb + (mat ? AT_SK : AT_SQ) + row * 128 +
                       ((uint32_t)(c16 * 16) ^ (uint32_t)((row & 7) << 4));
        if (row < Leff) {
            const __half* src = QKV + (size_t)ridx[row] * QKV_DIM + hoff +
                                (mat ? HIDDEN_DIM : 0) + c16 * 8;
            cp16(dst, src);
        } else {
            asm volatile("st.shared.v4.b32 [%0], {%1,%1,%1,%1};"
                         :: "r"(dst), "r"(0u) : "memory");
        }
    }
    cp_commit();
    cp_wait<0>();
    __syncthreads();

    // Phase 2: warps 0-3 compute score rows [16w, 16w+16) via mma + softmax
    if (wid < 4) {
        float cfr[8][4];
#pragma unroll
        for (int nt = 0; nt < 8; nt++)
#pragma unroll
            for (int r = 0; r < 4; r++) cfr[nt][r] = 0.f;

        const uint32_t swl = (uint32_t)((lane & 7) << 4);
        const uint32_t abase = sb + AT_SQ + (uint32_t)(16 * wid + (lane & 15)) * 128;
        const uint32_t ahi = (uint32_t)(((lane >> 4) & 1) * 16);
        const int brow = (lane & 7) + ((lane >> 4) & 1) * 8;
        const uint32_t bhi = (uint32_t)(((lane >> 3) & 1) * 16);

#pragma unroll
        for (int kf = 0; kf < 4; kf++) {
            uint32_t a0, a1, a2, a3, b[4][4];
            ldsm4(a0, a1, a2, a3, abase + (((uint32_t)(kf * 32) + ahi) ^ swl));
#pragma unroll
            for (int bt = 0; bt < 4; bt++)
                ldsm4(b[bt][0], b[bt][1], b[bt][2], b[bt][3],
                      sb + AT_SK + (uint32_t)(bt * 16 + brow) * 128 +
                          (((uint32_t)(kf * 32) + bhi) ^ swl));
#pragma unroll
            for (int nt = 0; nt < 8; nt++)
                mma16816(cfr[nt], a0, a1, a2, a3,
                         b[nt >> 1][(nt & 1) * 2], b[nt >> 1][(nt & 1) * 2 + 1]);
        }

        float m0 = -1e30f, m1 = -1e30f;
#pragma unroll
        for (int nt = 0; nt < 8; nt++)
#pragma unroll
            for (int rg = 0; rg < 2; rg++) {
                int col = nt * 8 + (lane & 3) * 2 + rg;
                if (col < Leff) {
                    m0 = fmaxf(m0, cfr[nt][rg] * 0.125f);
                    m1 = fmaxf(m1, cfr[nt][2 + rg] * 0.125f);
                }
            }
        m0 = fmaxf(m0, __shfl_xor_sync(0xffffffffu, m0, 1));
        m0 = fmaxf(m0, __shfl_xor_sync(0xffffffffu, m0, 2));
        m1 = fmaxf(m1, __shfl_xor_sync(0xffffffffu, m1, 1));
        m1 = fmaxf(m1, __shfl_xor_sync(0xffffffffu, m1, 2));

        float s0 = 0.f, s1 = 0.f;
#pragma unroll
        for (int nt = 0; nt < 8; nt++)
#pragma unroll
            for (int rg = 0; rg < 2; rg++) {
                int col = nt * 8 + (lane & 3) * 2 + rg;
                float e0 = (col < Leff) ? __expf(cfr[nt][rg] * 0.125f - m0) : 0.f;
                float e1 = (col < Leff) ? __expf(cfr[nt][2 + rg] * 0.125f - m1) : 0.f;
                cfr[nt][rg] = e0;
                cfr[nt][2 + rg] = e1;
                s0 += e0; s1 += e1;
            }
        s0 += __shfl_xor_sync(0xffffffffu, s0, 1);
        s0 += __shfl_xor_sync(0xffffffffu, s0, 2);
        s1 += __shfl_xor_sync(0xffffffffu, s1, 1);
        s1 += __shfl_xor_sync(0xffffffffu, s1, 2);
        float i0 = 1.f / s0, i1 = 1.f / s1;

        int row0 = 16 * wid + (lane >> 2);
#pragma unroll
        for (int nt = 0; nt < 8; nt++)
#pragma unroll
            for (int rg = 0; rg < 2; rg++) {
                int col = nt * 8 + (lane & 3) * 2 + rg;
                ps[row0 * 68 + col] = cfr[nt][rg] * i0;
                ps[(row0 + 8) * 68 + col] = cfr[nt][2 + rg] * i1;
            }
    }
    __syncthreads();

    // Phase 3: column mean over valid query rows
    if (tid < 64) {
        float s = 0.f;
        for (int ll = 0; ll < Leff; ll++) s += ps[ll * 68 + tid];
        wsum[tid] = s / (float)Leff;
    }
    __syncthreads();

    // Phase 4: pooled[d] = sum_{m<Leff} wsum[m] * V[m][d]  (V fp16; out fp16)
    const int pt = tid >> 6, d = tid & 63;
    float acc = 0.f;
    for (int m = pt; m < Leff; m += 4)
        acc = fmaf(wsum[m],
                   __half2float(QKV[(size_t)ridx[m] * QKV_DIM + 2 * HIDDEN_DIM + hoff + d]),
                   acc);
    part[pt * 64 + d] = acc;
    __syncthreads();
    if (tid < 64)
        pooled[(size_t)c * HIDDEN_DIM + hoff + tid] = __float2half(
            part[0 * 64 + tid] + part[1 * 64 + tid] + part[2 * 64 + tid] + part[3 * 64 + tid]);
}

// ---------------------------------------------------------------------------
// Launch (single stream, R12 ordering)
// ---------------------------------------------------------------------------
extern "C" void kernel_launch(void* const* d_in, const int* in_sizes, int n_in,
                              void* d_out, int out_size) {
    const float* chunk = (const float*)d_in[0];
    const float* Wq   = (const float*)d_in[1];
    const float* bq   = (const float*)d_in[2];
    const float* Wk   = (const float*)d_in[3];
    const float* bk   = (const float*)d_in[4];
    const float* Wv   = (const float*)d_in[5];
    const float* bv   = (const float*)d_in[6];
    const float* W_in = (const float*)d_in[7];
    const float* b_in = (const float*)d_in[8];
    const float* Wo   = (const float*)d_in[9];
    const float* bo   = (const float*)d_in[10];
    const float* Wout = (const float*)d_in[11];
    const float* bout = (const float*)d_in[12];
    const void*  cidx = d_in[13];
    const void*  clen = d_in[14];
    float* out = (float*)d_out;

    __half *pQKV, *pPooled;
    float *pbeff, *pbfinal;
    cudaGetSymbolAddress((void**)&pQKV, g_QKV);
    cudaGetSymbolAddress((void**)&pPooled, g_pooled);
    cudaGetSymbolAddress((void**)&pbeff, g_beff);
    cudaGetSymbolAddress((void**)&pbfinal, g_bfinal);

    static bool attr_set = false;
    if (!attr_set) {
        cudaFuncSetAttribute(qkv_mma_kernel, cudaFuncAttributeMaxDynamicSharedMemorySize,
                             SMEM_MMA);
        cudaFuncSetAttribute(out_mma_kernel, cudaFuncAttributeMaxDynamicSharedMemorySize,
                             SMEM_MMA);
        attr_set = true;
    }

    // 0+1) dtype detection + combined biases (merged)
    setup_kernel<<<(QKV_DIM + OUTPUT_DIM + 1 + 255) / 256, 256>>>(
        (const int*)cidx, (const int*)clen,
        W_in, b_in, bq, bk, bv, Wout, bo, bout, pbeff, pbfinal);

    // 2) merged small GEMMs (Weff + Wfinal) + merged reduce (emit fp16)
    weights_part_kernel<<<dim3(INPUT_DIM / 128, HIDDEN_DIM / 128, 16), 256>>>(
        W_in, Wq, Wk, Wv, Wout, Wo);
    reduce_weights_kernel<<<(unsigned)((N_WEFF4 + N_WFIN4 + 255) / 256), 256>>>();

    // 3) chunk -> fp16
    convert_chunk_kernel<<<((size_t)M_PAD * INPUT_DIM / 8 + 255) / 256, 256>>>(chunk);

    // 4) QKV projection (8-warp R11 config, fp16 output)
    qkv_mma_kernel<<<dim3(QKV_DIM / 128, M_PAD / 128), 256, SMEM_MMA>>>(pbeff, pQKV);

    // 5) fused attention + masked mean pool (single-head, pooled fp16)
    attn_pool_kernel<<<dim3(NUM_CELLS, NUM_HEADS), 256>>>(pQKV, cidx, clen, pPooled);

    // 6) final projection via mma
    out_mma_kernel<<<dim3(OUTPUT_DIM / 128, NUM_CELLS / 128), 256, SMEM_MMA>>>(pbfinal, out);
}

// round 15
// speedup vs baseline: 1.1678x; 1.0927x over previous
#include <cuda_runtime.h>
#include <cuda_fp16.h>
#include <cuda_bf16.h>
#include <math.h>
#include <stdint.h>

// ---------------------------------------------------------------------------
// Problem constants
// ---------------------------------------------------------------------------
#define NUM_HEADS   8
#define NUM_CHUNKS  50000
#define INPUT_DIM   768
#define HIDDEN_DIM  512
#define OUTPUT_DIM  256
#define NUM_CELLS   2048
#define MAX_LEN     64
#define HEAD_DIM    64
#define QKV_DIM     1536
#define M_PAD       50048              // 391 * 128
#define SPLITK      4

// mma GEMM geometry (k-chunk 64, swizzled smem, 3 stages, 2 CTA/SM)
#define CHUNK_K     64
#define NCHUNKS     12                 // single fp16 pass: 768/64
#define NCHUNKS_O   8                  // final projection: 512/64
#define TILE_BYTES  (128 * 128)        // 16384 (128 rows x 128B swizzled)
#define STAGE_B     (2 * TILE_BYTES)   // 32768
#define SMEM_MMA    (3 * STAGE_B)      // 98304

// ---------------------------------------------------------------------------
// Device-global scratch (allocation-free contract)
// ---------------------------------------------------------------------------
__device__ __align__(1024) __half g_Ahi[(size_t)M_PAD * INPUT_DIM];
__device__ __align__(1024) __half g_Bhi[QKV_DIM * INPUT_DIM];
__device__ __align__(1024) __half g_QKV[(size_t)NUM_CHUNKS * QKV_DIM];
__device__ __align__(1024) __half g_pooled[NUM_CELLS * HIDDEN_DIM];
__device__ __align__(1024) __half g_Wfinalh[OUTPUT_DIM * HIDDEN_DIM];
__device__ __align__(256) float g_beff[QKV_DIM];
__device__ __align__(256) float g_bfinal[OUTPUT_DIM];
__device__ __align__(256) float g_WeffPart[SPLITK * QKV_DIM * INPUT_DIM];
__device__ __align__(256) float g_WfinalPart[SPLITK * OUTPUT_DIM * HIDDEN_DIM];
__device__ int g_idx_is64;
__device__ int g_len_is64;

// ---------------------------------------------------------------------------
// PTX helpers (plain-sm_80-level: safe for non-'a' ptx target)
// ---------------------------------------------------------------------------
__device__ __forceinline__ uint32_t smem_u32(const void* p) {
    uint32_t a;
    asm("{ .reg .u64 t; cvta.to.shared.u64 t, %1; cvt.u32.u64 %0, t; }"
        : "=r"(a) : "l"(p));
    return a;
}
__device__ __forceinline__ void cp16(uint32_t d, const void* s) {
    asm volatile("cp.async.cg.shared.global [%0], [%1], 16;" :: "r"(d), "l"(s));
}
__device__ __forceinline__ void cp_commit() {
    asm volatile("cp.async.commit_group;" ::: "memory");
}
template <int N>
__device__ __forceinline__ void cp_wait() {
    asm volatile("cp.async.wait_group %0;" :: "n"(N) : "memory");
}
__device__ __forceinline__ void ldsm4(uint32_t& r0, uint32_t& r1, uint32_t& r2,
                                      uint32_t& r3, uint32_t a) {
    asm volatile("ldmatrix.sync.aligned.m8n8.x4.shared.b16 {%0,%1,%2,%3}, [%4];"
                 : "=r"(r0), "=r"(r1), "=r"(r2), "=r"(r3) : "r"(a));
}
__device__ __forceinline__ void mma16816(float* c, uint32_t a0, uint32_t a1,
                                         uint32_t a2, uint32_t a3,
                                         uint32_t b0, uint32_t b1) {
    asm volatile("mma.sync.aligned.m16n8k16.row.col.f32.f16.f16.f32 "
                 "{%0,%1,%2,%3}, {%4,%5,%6,%7}, {%8,%9}, {%0,%1,%2,%3};"
                 : "+f"(c[0]), "+f"(c[1]), "+f"(c[2]), "+f"(c[3])
                 : "r"(a0), "r"(a1), "r"(a2), "r"(a3), "r"(b0), "r"(b1));
}
__device__ __forceinline__ uint32_t packh2(float a, float b) {
    __half2 h = __floats2half2_rn(a, b);
    return *(uint32_t*)&h;
}

// ---------------------------------------------------------------------------
// dtype detection + combined biases (merged, one launch)
// ---------------------------------------------------------------------------
__global__ void setup_kernel(const int* __restrict__ iw, const int* __restrict__ lw,
                             const float* __restrict__ W_in, const float* __restrict__ b_in,
                             const float* __restrict__ bq, const float* __restrict__ bk,
                             const float* __restrict__ bv, const float* __restrict__ Wout,
                             const float* __restrict__ bo, const float* __restrict__ bout,
                             float* __restrict__ beff, float* __restrict__ bfinal) {
    int i = blockIdx.x * blockDim.x + threadIdx.x;
    if (i == QKV_DIM + OUTPUT_DIM) {
        int oi = 0, ol = 0;
        for (int k = 0; k < 256; k++) oi |= iw[2 * k + 1];
        for (int k = 0; k < 256; k++) ol |= lw[2 * k + 1];
        g_idx_is64 = (oi == 0) ? 1 : 0;
        g_len_is64 = (ol == 0) ? 1 : 0;
        return;
    }
    if (i < QKV_DIM) {
        const float* bs = (i < HIDDEN_DIM) ? bq : (i < 2 * HIDDEN_DIM ? bk : bv);
        const float* w = W_in + (size_t)i * HIDDEN_DIM;
        float s = 0.f;
        for (int k = 0; k < HIDDEN_DIM; k++) s = fmaf(w[k], bs[k], s);
        beff[i] = s + b_in[i];
    } else if (i < QKV_DIM + OUTPUT_DIM) {
        int o = i - QKV_DIM;
        const float* w = Wout + (size_t)o * HIDDEN_DIM;
        float s = 0.f;
        for (int k = 0; k < HIDDEN_DIM; k++) s = fmaf(w[k], bo[k], s);
        bfinal[o] = s + bout[o];
    }
}

// ---------------------------------------------------------------------------
// SIMT tile GEMM body (128x128, 8x8/thread). Small split-K GEMMs.
// ---------------------------------------------------------------------------
__device__ __forceinline__ void sgemm_tile_nn(int Klen, int lda, int ldb, int ldc,
                                              const float* __restrict__ A,
                                              const float* __restrict__ B,
                                              float* __restrict__ C, int bm, int bn) {
    __shared__ float As[8][128];
    __shared__ float Bs[8][128];
    const int tid = threadIdx.x;
    const int tx = tid & 15, ty = tid >> 4;
    float acc[8][8];
#pragma unroll
    for (int i = 0; i < 8; i++)
#pragma unroll
        for (int j = 0; j < 8; j++) acc[i][j] = 0.f;

    const int arow = tid >> 1, ak = (tid & 1) * 4;
    const int bkr = tid >> 5, bnc = (tid & 31) * 4;

    for (int k0 = 0; k0 < Klen; k0 += 8) {
        float4 av = *(const float4*)(A + (size_t)(bm + arow) * lda + k0 + ak);
        As[ak + 0][arow] = av.x; As[ak + 1][arow] = av.y;
        As[ak + 2][arow] = av.z; As[ak + 3][arow] = av.w;
        float4 bv = *(const float4*)(B + (size_t)(k0 + bkr) * ldb + bn + bnc);
        *(float4*)&Bs[bkr][bnc] = bv;
        __syncthreads();
#pragma unroll
        for (int kk = 0; kk < 8; kk++) {
            float a[8], b[8];
            *(float4*)&a[0] = *(const float4*)&As[kk][ty * 8];
            *(float4*)&a[4] = *(const float4*)&As[kk][ty * 8 + 4];
            *(float4*)&b[0] = *(const float4*)&Bs[kk][tx * 8];
            *(float4*)&b[4] = *(const float4*)&Bs[kk][tx * 8 + 4];
#pragma unroll
            for (int i = 0; i < 8; i++)
#pragma unroll
                for (int j = 0; j < 8; j++) acc[i][j] = fmaf(a[i], b[j], acc[i][j]);
        }
        __syncthreads();
    }
#pragma unroll
    for (int i = 0; i < 8; i++) {
        int row = bm + ty * 8 + i;
#pragma unroll
        for (int j = 0; j < 8; j += 4) {
            int col = bn + tx * 8 + j;
            *(float4*)(C + (size_t)row * ldc + col) = *(float4*)&acc[i][j];
        }
    }
}

// Merged Weff + Wfinal partials in ONE launch.
__global__ void __launch_bounds__(256)
weights_part_kernel(const float* __restrict__ W_in, const float* __restrict__ Wq,
                    const float* __restrict__ Wk, const float* __restrict__ Wv,
                    const float* __restrict__ Wout, const float* __restrict__ Wo) {
    int z = blockIdx.z;
    if (z < 12) {
        int t = z >> 2, sl = z & 3;
        const float* Bt = (t == 0) ? Wq : (t == 1 ? Wk : Wv);
        const float* A = W_in + (size_t)t * HIDDEN_DIM * HIDDEN_DIM + sl * 128;
        const float* B = Bt + (size_t)sl * 128 * INPUT_DIM;
        float* C = g_WeffPart + (size_t)sl * QKV_DIM * INPUT_DIM +
                   (size_t)t * HIDDEN_DIM * INPUT_DIM;
        sgemm_tile_nn(128, HIDDEN_DIM, INPUT_DIM, INPUT_DIM, A, B, C,
                      blockIdx.y * 128, blockIdx.x * 128);
    } else {
        if (blockIdx.x >= HIDDEN_DIM / 128 || blockIdx.y >= OUTPUT_DIM / 128) return;
        int sl = z - 12;
        sgemm_tile_nn(128, HIDDEN_DIM, HIDDEN_DIM, HIDDEN_DIM,
                      Wout + sl * 128, Wo + (size_t)sl * 128 * HIDDEN_DIM,
                      g_WfinalPart + (size_t)sl * OUTPUT_DIM * HIDDEN_DIM,
                      blockIdx.y * 128, blockIdx.x * 128);
    }
}

// ---------------------------------------------------------------------------
// Merged reduction: Weff partials -> fp16 B; Wfinal partials -> fp16
// ---------------------------------------------------------------------------
#define N_WEFF4  ((size_t)QKV_DIM * INPUT_DIM / 4)     // 294912
#define N_WFIN4  ((size_t)OUTPUT_DIM * HIDDEN_DIM / 4) // 32768
__global__ void reduce_weights_kernel() {
    size_t i = (size_t)blockIdx.x * blockDim.x + threadIdx.x;
    if (i < N_WEFF4) {
        const size_t stride = (size_t)QKV_DIM * INPUT_DIM;
        float4 s = *(const float4*)(g_WeffPart + i * 4);
#pragma unroll
        for (int p = 1; p < SPLITK; p++) {
            float4 v = *(const float4*)(g_WeffPart + p * stride + i * 4);
            s.x += v.x; s.y += v.y; s.z += v.z; s.w += v.w;
        }
        uint2 h;
        h.x = packh2(s.x, s.y); h.y = packh2(s.z, s.w);
        *(uint2*)(g_Bhi + i * 4) = h;
    } else if (i < N_WEFF4 + N_WFIN4) {
        size_t j = i - N_WEFF4;
        const size_t stride = (size_t)OUTPUT_DIM * HIDDEN_DIM;
        float4 s = *(const float4*)(g_WfinalPart + j * 4);
#pragma unroll
        for (int p = 1; p < SPLITK; p++) {
            float4 v = *(const float4*)(g_WfinalPart + p * stride + j * 4);
            s.x += v.x; s.y += v.y; s.z += v.z; s.w += v.w;
        }
        uint2 h;
        h.x = packh2(s.x, s.y); h.y = packh2(s.z, s.w);
        *(uint2*)(g_Wfinalh + j * 4) = h;
    }
}

// ---------------------------------------------------------------------------
// chunk fp32 -> fp16 (rows >= NUM_CHUNKS zero-padded to M_PAD)
// ---------------------------------------------------------------------------
__global__ void convert_chunk_kernel(const float* __restrict__ x) {
    size_t i = (size_t)blockIdx.x * blockDim.x + threadIdx.x;
    const size_t n8 = (size_t)M_PAD * INPUT_DIM / 8;
    if (i >= n8) return;
    uint4 out = make_uint4(0, 0, 0, 0);
    if (i * 8 < (size_t)NUM_CHUNKS * INPUT_DIM) {
        float4 v0 = *(const float4*)(x + i * 8);
        float4 v1 = *(const float4*)(x + i * 8 + 4);
        out.x = packh2(v0.x, v0.y); out.y = packh2(v0.z, v0.w);
        out.z = packh2(v1.x, v1.y); out.w = packh2(v1.z, v1.w);
    }
    *(uint4*)(g_Ahi + i * 8) = out;
}

// ---------------------------------------------------------------------------
// QKV GEMM via mma.sync fp16 (R11-proven 8-warp config). fp16 out.
// ---------------------------------------------------------------------------
__global__ void __launch_bounds__(256, 2)
qkv_mma_kernel(const float* __restrict__ beff, __half* __restrict__ C) {
    extern __shared__ __align__(128) char smem[];
    const uint32_t sb = smem_u32(smem);
    const int tid = threadIdx.x, lane = tid & 31, wid = tid >> 5;
    const int bm = blockIdx.y * 128, bn = blockIdx.x * 128;
    const int wm = (wid & 1) * 64, wn = (wid >> 1) * 32;

    float c[4][4][4];
#pragma unroll
    for (int mt = 0; mt < 4; mt++)
#pragma unroll
        for (int nt = 0; nt < 4; nt++)
#pragma unroll
            for (int r = 0; r < 4; r++) c[mt][nt][r] = 0.f;

    const uint32_t sw   = (uint32_t)((lane & 7) << 4);
    const int arow = wm + (lane & 15);
    const uint32_t ahi  = (uint32_t)(((lane >> 4) & 1) * 16);
    const int brow = wn + (lane & 7) + ((lane >> 4) & 1) * 8;
    const uint32_t bhi  = (uint32_t)(((lane >> 3) & 1) * 16);

    auto issue = [&](int chunk) {
        int st = chunk % 3;
        int ko = chunk * CHUNK_K;
        uint32_t base = sb + st * STAGE_B;
#pragma unroll
        for (int i = 0; i < 8; i++) {
            int u = tid + 256 * i;
            int row = (u >> 3) & 127;
            int c16 = u & 7;
            bool isB = u >= 1024;
            uint32_t dst = base + (isB ? TILE_BYTES : 0) + row * 128 +
                           ((uint32_t)(c16 * 16) ^ (uint32_t)((row & 7) << 4));
            const __half* src =
                isB ? g_Bhi + (size_t)(bn + row) * INPUT_DIM + ko + c16 * 8
                    : g_Ahi + (size_t)(bm + row) * INPUT_DIM + ko + c16 * 8;
            cp16(dst, src);
        }
        cp_commit();
    };

    issue(0);
    issue(1);

    for (int i = 0; i < NCHUNKS; i++) {
        cp_wait<1>();
        __syncthreads();
        if (i + 2 < NCHUNKS) issue(i + 2);
        else cp_commit();
        uint32_t sa = sb + (i % 3) * STAGE_B;
        uint32_t sB = sa + TILE_BYTES;
#pragma unroll
        for (int kf = 0; kf < 4; kf++) {
            uint32_t a[4][4], b[2][4];
#pragma unroll
            for (int mt = 0; mt < 4; mt++)
                ldsm4(a[mt][0], a[mt][1], a[mt][2], a[mt][3],
                      sa + (uint32_t)(arow + mt * 16) * 128 +
                          (((uint32_t)(kf * 32) + ahi) ^ sw));
#pragma unroll
            for (int bt = 0; bt < 2; bt++)
                ldsm4(b[bt][0], b[bt][1], b[bt][2], b[bt][3],
                      sB + (uint32_t)(brow + bt * 16) * 128 +
                          (((uint32_t)(kf * 32) + bhi) ^ sw));
#pragma unroll
            for (int mt = 0; mt < 4; mt++)
#pragma unroll
                for (int nt = 0; nt < 4; nt++)
                    mma16816(c[mt][nt], a[mt][0], a[mt][1], a[mt][2], a[mt][3],
                             b[nt >> 1][(nt & 1) * 2], b[nt >> 1][(nt & 1) * 2 + 1]);
        }
    }

    const int rr = bm + wm + (lane >> 2);
    const int cc = bn + wn + (lane & 3) * 2;
#pragma unroll
    for (int mt = 0; mt < 4; mt++) {
#pragma unroll
        for (int nt = 0; nt < 4; nt++) {
            int col = cc + nt * 8;
            float b0 = beff[col], b1 = beff[col + 1];
            int row = rr + mt * 16;
            if (row < NUM_CHUNKS) {
                uint32_t v = packh2(c[mt][nt][0] + b0, c[mt][nt][1] + b1);
                *(uint32_t*)(C + (size_t)row * QKV_DIM + col) = v;
            }
            if (row + 8 < NUM_CHUNKS) {
                uint32_t v = packh2(c[mt][nt][2] + b0, c[mt][nt][3] + b1);
                *(uint32_t*)(C + (size_t)(row + 8) * QKV_DIM + col) = v;
            }
        }
    }
}

// ---------------------------------------------------------------------------
// Final projection via mma.sync fp16 (R12-proven):
// out[2048,256] = pooled[2048,512](fp16) @ Wfinalh[256,512]^T + bfinal
// ---------------------------------------------------------------------------
__global__ void __launch_bounds__(256, 2)
out_mma_kernel(const float* __restrict__ bfinal, float* __restrict__ C) {
    extern __shared__ __align__(128) char smem[];
    const uint32_t sb = smem_u32(smem);
    const int tid = threadIdx.x, lane = tid & 31, wid = tid >> 5;
    const int bm = blockIdx.y * 128, bn = blockIdx.x * 128;
    const int wm = (wid & 1) * 64, wn = (wid >> 1) * 32;

    float c[4][4][4];
#pragma unroll
    for (int mt = 0; mt < 4; mt++)
#pragma unroll
        for (int nt = 0; nt < 4; nt++)
#pragma unroll
            for (int r = 0; r < 4; r++) c[mt][nt][r] = 0.f;

    const uint32_t sw   = (uint32_t)((lane & 7) << 4);
    const int arow = wm + (lane & 15);
    const uint32_t ahi  = (uint32_t)(((lane >> 4) & 1) * 16);
    const int brow = wn + (lane & 7) + ((lane >> 4) & 1) * 8;
    const uint32_t bhi  = (uint32_t)(((lane >> 3) & 1) * 16);

    auto issue = [&](int chunk) {
        int st = chunk % 3;
        int ko = chunk * CHUNK_K;
        uint32_t base = sb + st * STAGE_B;
#pragma unroll
        for (int i = 0; i < 8; i++) {
            int u = tid + 256 * i;
            int row = (u >> 3) & 127;
            int c16 = u & 7;
            bool isB = u >= 1024;
            uint32_t dst = base + (isB ? TILE_BYTES : 0) + row * 128 +
                           ((uint32_t)(c16 * 16) ^ (uint32_t)((row & 7) << 4));
            const __half* src =
                isB ? g_Wfinalh + (size_t)(bn + row) * HIDDEN_DIM + ko + c16 * 8
                    : g_pooled + (size_t)(bm + row) * HIDDEN_DIM + ko + c16 * 8;
            cp16(dst, src);
        }
        cp_commit();
    };

    issue(0);
    issue(1);

    for (int i = 0; i < NCHUNKS_O; i++) {
        cp_wait<1>();
        __syncthreads();
        if (i + 2 < NCHUNKS_O) issue(i + 2);
        else cp_commit();
        uint32_t sa = sb + (i % 3) * STAGE_B;
        uint32_t sB = sa + TILE_BYTES;
#pragma unroll
        for (int kf = 0; kf < 4; kf++) {
            uint32_t a[4][4], b[2][4];
#pragma unroll
            for (int mt = 0; mt < 4; mt++)
                ldsm4(a[mt][0], a[mt][1], a[mt][2], a[mt][3],
                      sa + (uint32_t)(arow + mt * 16) * 128 +
                          (((uint32_t)(kf * 32) + ahi) ^ sw));
#pragma unroll
            for (int bt = 0; bt < 2; bt++)
                ldsm4(b[bt][0], b[bt][1], b[bt][2], b[bt][3],
                      sB + (uint32_t)(brow + bt * 16) * 128 +
                          (((uint32_t)(kf * 32) + bhi) ^ sw));
#pragma unroll
            for (int mt = 0; mt < 4; mt++)
#pragma unroll
                for (int nt = 0; nt < 4; nt++)
                    mma16816(c[mt][nt], a[mt][0], a[mt][1], a[mt][2], a[mt][3],
                             b[nt >> 1][(nt & 1) * 2], b[nt >> 1][(nt & 1) * 2 + 1]);
        }
    }

    const int rr = bm + wm + (lane >> 2);
    const int cc = bn + wn + (lane & 3) * 2;
#pragma unroll
    for (int mt = 0; mt < 4; mt++) {
#pragma unroll
        for (int nt = 0; nt < 4; nt++) {
            int col = cc + nt * 8;
            float b0 = bfinal[col], b1 = bfinal[col + 1];
            int row = rr + mt * 16;
            float2 v0 = make_float2(c[mt][nt][0] + b0, c[mt][nt][1] + b1);
            *(float2*)(C + (size_t)row * OUTPUT_DIM + col) = v0;
            float2 v1 = make_float2(c[mt][nt][2] + b0, c[mt][nt][3] + b1);
            *(float2*)(C + (size_t)(row + 8) * OUTPUT_DIM + col) = v1;
        }
    }
}

// ---------------------------------------------------------------------------
// Attention + masked mean pool: 128 threads (4 warps all active in scores),
// probs stored fp16 -> 26.6KB smem -> 8 CTAs/SM (was 6).
// ---------------------------------------------------------------------------
#define AT_SQ    0        // 8192: Q fp16, 64 rows x 128B, swizzled
#define AT_SK    8192     // 8192: K fp16
#define AT_PS    16384    // 64*72*2 = 9216: probs fp16 (row stride 72 halfs)
#define AT_WS    25600    // 64*4: wsum
#define AT_PART  25856    // 2*64*4: partial pooled
#define AT_RIDX  26368    // 64*4: gathered indices
#define AT_TOTAL 26624

__global__ void __launch_bounds__(128)
attn_pool_kernel(const __half* __restrict__ QKV, const void* __restrict__ cell_idx,
                 const void* __restrict__ cell_len, __half* __restrict__ pooled) {
    __shared__ __align__(128) char sm[AT_TOTAL];
    const uint32_t sb = smem_u32(sm);
    __half* psh = (__half*)(sm + AT_PS);     // [64][72]
    float* wsum = (float*)(sm + AT_WS);
    float* part = (float*)(sm + AT_PART);    // [2][64]
    int*   ridx = (int*)(sm + AT_RIDX);

    const int c = blockIdx.x, h = blockIdx.y, tid = threadIdx.x;
    const int lane = tid & 31, wid = tid >> 5;
    const int hoff = h * HEAD_DIM;
    const int sI = g_idx_is64 ? 2 : 1;
    const int sL = g_len_is64 ? 2 : 1;
    const int* idx32 = (const int*)cell_idx;
    const int* len32 = (const int*)cell_len;

    int len = len32[(size_t)c * sL];
    int Leff = len < 1 ? 1 : (len > 64 ? 64 : len);
    if (tid < 64) ridx[tid] = idx32[((size_t)c * MAX_LEN + tid) * sI];
    __syncthreads();

    // Phase 1: gather Q,K fp16 via cp.async (zero rows >= Leff).
    // 1024 16B units, 128 threads -> 8 units/thread.
#pragma unroll
    for (int it = 0; it < 8; it++) {
        int u = tid + 128 * it;
        int mat = u >> 9;                  // 0 = Q, 1 = K
        int idx = u & 511;
        int row = idx >> 3, c16 = idx & 7;
        uint32_t dst = sb + (mat ? AT_SK : AT_SQ) + row * 128 +
                       ((uint32_t)(c16 * 16) ^ (uint32_t)((row & 7) << 4));
        if (row < Leff) {
            const __half* src = QKV + (size_t)ridx[row] * QKV_DIM + hoff +
                                (mat ? HIDDEN_DIM : 0) + c16 * 8;
            cp16(dst, src);
        } else {
            asm volatile("st.shared.v4.b32 [%0], {%1,%1,%1,%1};"
                         :: "r"(dst), "r"(0u) : "memory");
        }
    }
    cp_commit();
    cp_wait<0>();
    __syncthreads();

    // Phase 2: ALL 4 warps compute score rows [16w, 16w+16) via mma + softmax
    {
        float cfr[8][4];
#pragma unroll
        for (int nt = 0; nt < 8; nt++)
#pragma unroll
            for (int r = 0; r < 4; r++) cfr[nt][r] = 0.f;

        const uint32_t swl = (uint32_t)((lane & 7) << 4);
        const uint32_t abase = sb + AT_SQ + (uint32_t)(16 * wid + (lane & 15)) * 128;
        const uint32_t ahi = (uint32_t)(((lane >> 4) & 1) * 16);
        const int brow = (lane & 7) + ((lane >> 4) & 1) * 8;
        const uint32_t bhi = (uint32_t)(((lane >> 3) & 1) * 16);

#pragma unroll
        for (int kf = 0; kf < 4; kf++) {
            uint32_t a0, a1, a2, a3, b[4][4];
            ldsm4(a0, a1, a2, a3, abase + (((uint32_t)(kf * 32) + ahi) ^ swl));
#pragma unroll
            for (int bt = 0; bt < 4; bt++)
                ldsm4(b[bt][0], b[bt][1], b[bt][2], b[bt][3],
                      sb + AT_SK + (uint32_t)(bt * 16 + brow) * 128 +
                          (((uint32_t)(kf * 32) + bhi) ^ swl));
#pragma unroll
            for (int nt = 0; nt < 8; nt++)
                mma16816(cfr[nt], a0, a1, a2, a3,
                         b[nt >> 1][(nt & 1) * 2], b[nt >> 1][(nt & 1) * 2 + 1]);
        }

        float m0 = -1e30f, m1 = -1e30f;
#pragma unroll
        for (int nt = 0; nt < 8; nt++)
#pragma unroll
            for (int rg = 0; rg < 2; rg++) {
                int col = nt * 8 + (lane & 3) * 2 + rg;
                if (col < Leff) {
                    m0 = fmaxf(m0, cfr[nt][rg] * 0.125f);
                    m1 = fmaxf(m1, cfr[nt][2 + rg] * 0.125f);
                }
            }
        m0 = fmaxf(m0, __shfl_xor_sync(0xffffffffu, m0, 1));
        m0 = fmaxf(m0, __shfl_xor_sync(0xffffffffu, m0, 2));
        m1 = fmaxf(m1, __shfl_xor_sync(0xffffffffu, m1, 1));
        m1 = fmaxf(m1, __shfl_xor_sync(0xffffffffu, m1, 2));

        float s0 = 0.f, s1 = 0.f;
#pragma unroll
        for (int nt = 0; nt < 8; nt++)
#pragma unroll
            for (int rg = 0; rg < 2; rg++) {
                int col = nt * 8 + (lane & 3) * 2 + rg;
                float e0 = (col < Leff) ? __expf(cfr[nt][rg] * 0.125f - m0) : 0.f;
                float e1 = (col < Leff) ? __expf(cfr[nt][2 + rg] * 0.125f - m1) : 0.f;
                cfr[nt][rg] = e0;
                cfr[nt][2 + rg] = e1;
                s0 += e0; s1 += e1;
            }
        s0 += __shfl_xor_sync(0xffffffffu, s0, 1);
        s0 += __shfl_xor_sync(0xffffffffu, s0, 2);
        s1 += __shfl_xor_sync(0xffffffffu, s1, 1);
        s1 += __shfl_xor_sync(0xffffffffu, s1, 2);
        float i0 = 1.f / s0, i1 = 1.f / s1;

        int row0 = 16 * wid + (lane >> 2);
#pragma unroll
        for (int nt = 0; nt < 8; nt++)
#pragma unroll
            for (int rg = 0; rg < 2; rg++) {
                int col = nt * 8 + (lane & 3) * 2 + rg;
                psh[row0 * 72 + col] = __float2half(cfr[nt][rg] * i0);
                psh[(row0 + 8) * 72 + col] = __float2half(cfr[nt][2 + rg] * i1);
            }
    }
    __syncthreads();

    // Phase 3: column mean over valid query rows (64 of 128 threads)
    if (tid < 64) {
        float s = 0.f;
        for (int ll = 0; ll < Leff; ll++) s += __half2float(psh[ll * 72 + tid]);
        wsum[tid] = s / (float)Leff;
    }
    __syncthreads();

    // Phase 4: pooled[d] = sum_{m<Leff} wsum[m] * V[m][d]; 2 partitions x 64
    {
        int pt = tid >> 6, d = tid & 63;
        float acc = 0.f;
        for (int m = pt; m < Leff; m += 2)
            acc = fmaf(wsum[m],
                       __half2float(QKV[(size_t)ridx[m] * QKV_DIM + 2 * HIDDEN_DIM + hoff + d]),
                       acc);
        part[pt * 64 + d] = acc;
    }
    __syncthreads();
    if (tid < 64)
        pooled[(size_t)c * HIDDEN_DIM + hoff + tid] =
            __float2half(part[tid] + part[64 + tid]);
}

// ---------------------------------------------------------------------------
// Launch (single stream, R14 ordering)
// ---------------------------------------------------------------------------
extern "C" void kernel_launch(void* const* d_in, const int* in_sizes, int n_in,
                              void* d_out, int out_size) {
    const float* chunk = (const float*)d_in[0];
    const float* Wq   = (const float*)d_in[1];
    const float* bq   = (const float*)d_in[2];
    const float* Wk   = (const float*)d_in[3];
    const float* bk   = (const float*)d_in[4];
    const float* Wv   = (const float*)d_in[5];
    const float* bv   = (const float*)d_in[6];
    const float* W_in = (const float*)d_in[7];
    const float* b_in = (const float*)d_in[8];
    const float* Wo   = (const float*)d_in[9];
    const float* bo   = (const float*)d_in[10];
    const float* Wout = (const float*)d_in[11];
    const float* bout = (const float*)d_in[12];
    const void*  cidx = d_in[13];
    const void*  clen = d_in[14];
    float* out = (float*)d_out;

    __half *pQKV, *pPooled;
    float *pbeff, *pbfinal;
    cudaGetSymbolAddress((void**)&pQKV, g_QKV);
    cudaGetSymbolAddress((void**)&pPooled, g_pooled);
    cudaGetSymbolAddress((void**)&pbeff, g_beff);
    cudaGetSymbolAddress((void**)&pbfinal, g_bfinal);

    static bool attr_set = false;
    if (!attr_set) {
        cudaFuncSetAttribute(qkv_mma_kernel, cudaFuncAttributeMaxDynamicSharedMemorySize,
                             SMEM_MMA);
        cudaFuncSetAttribute(out_mma_kernel, cudaFuncAttributeMaxDynamicSharedMemorySize,
                             SMEM_MMA);
        attr_set = true;
    }

    // 0+1) dtype detection + combined biases (merged)
    setup_kernel<<<(QKV_DIM + OUTPUT_DIM + 1 + 255) / 256, 256>>>(
        (const int*)cidx, (const int*)clen,
        W_in, b_in, bq, bk, bv, Wout, bo, bout, pbeff, pbfinal);

    // 2) merged small GEMMs (Weff + Wfinal) + merged reduce (emit fp16)
    weights_part_kernel<<<dim3(INPUT_DIM / 128, HIDDEN_DIM / 128, 16), 256>>>(
        W_in, Wq, Wk, Wv, Wout, Wo);
    reduce_weights_kernel<<<(unsigned)((N_WEFF4 + N_WFIN4 + 255) / 256), 256>>>();

    // 3) chunk -> fp16
    convert_chunk_kernel<<<((size_t)M_PAD * INPUT_DIM / 8 + 255) / 256, 256>>>(chunk);

    // 4) QKV projection (8-warp R11 config, fp16 output)
    qkv_mma_kernel<<<dim3(QKV_DIM / 128, M_PAD / 128), 256, SMEM_MMA>>>(pbeff, pQKV);

    // 5) fused attention + masked mean pool (128 threads, 8 CTAs/SM)
    attn_pool_kernel<<<dim3(NUM_CELLS, NUM_HEADS), 128>>>(pQKV, cidx, clen, pPooled);

    // 6) final projection via mma
    out_mma_kernel<<<dim3(OUTPUT_DIM / 128, NUM_CELLS / 128), 256, SMEM_MMA>>>(pbfinal, out);
}

// round 16
// speedup vs baseline: 1.1949x; 1.0232x over previous
#include <cuda_runtime.h>
#include <cuda_fp16.h>
#include <cuda_bf16.h>
#include <math.h>
#include <stdint.h>

// ---------------------------------------------------------------------------
// Problem constants
// ---------------------------------------------------------------------------
#define NUM_HEADS   8
#define NUM_CHUNKS  50000
#define INPUT_DIM   768
#define HIDDEN_DIM  512
#define OUTPUT_DIM  256
#define NUM_CELLS   2048
#define MAX_LEN     64
#define HEAD_DIM    64
#define QKV_DIM     1536
#define M_PAD       50048              // 391 * 128
#define SPLITK      4

// mma GEMM geometry (k-chunk 64, swizzled smem, 3 stages, 2 CTA/SM)
#define CHUNK_K     64
#define NCHUNKS     12                 // single fp16 pass: 768/64
#define NCHUNKS_O   8                  // final projection: 512/64
#define TILE_BYTES  (128 * 128)        // 16384 (128 rows x 128B swizzled)
#define STAGE_B     (2 * TILE_BYTES)   // 32768
#define SMEM_MMA    (3 * STAGE_B)      // 98304

// ---------------------------------------------------------------------------
// Device-global scratch (allocation-free contract)
// ---------------------------------------------------------------------------
__device__ __align__(1024) __half g_Ahi[(size_t)M_PAD * INPUT_DIM];
__device__ __align__(1024) __half g_Bhi[QKV_DIM * INPUT_DIM];
__device__ __align__(1024) __half g_QKV[(size_t)NUM_CHUNKS * QKV_DIM];
__device__ __align__(1024) __half g_pooled[NUM_CELLS * HIDDEN_DIM];
__device__ __align__(1024) __half g_Wfinalh[OUTPUT_DIM * HIDDEN_DIM];
__device__ __align__(256) float g_beff[QKV_DIM];
__device__ __align__(256) float g_bfinal[OUTPUT_DIM];
__device__ __align__(256) float g_WeffPart[SPLITK * QKV_DIM * INPUT_DIM];
__device__ __align__(256) float g_WfinalPart[SPLITK * OUTPUT_DIM * HIDDEN_DIM];
__device__ int g_idx_is64;
__device__ int g_len_is64;

// ---------------------------------------------------------------------------
// PTX helpers (plain-sm_80-level: safe for non-'a' ptx target)
// ---------------------------------------------------------------------------
__device__ __forceinline__ uint32_t smem_u32(const void* p) {
    uint32_t a;
    asm("{ .reg .u64 t; cvta.to.shared.u64 t, %1; cvt.u32.u64 %0, t; }"
        : "=r"(a) : "l"(p));
    return a;
}
__device__ __forceinline__ void cp16(uint32_t d, const void* s) {
    asm volatile("cp.async.cg.shared.global [%0], [%1], 16;" :: "r"(d), "l"(s));
}
__device__ __forceinline__ void cp_commit() {
    asm volatile("cp.async.commit_group;" ::: "memory");
}
template <int N>
__device__ __forceinline__ void cp_wait() {
    asm volatile("cp.async.wait_group %0;" :: "n"(N) : "memory");
}
__device__ __forceinline__ void ldsm4(uint32_t& r0, uint32_t& r1, uint32_t& r2,
                                      uint32_t& r3, uint32_t a) {
    asm volatile("ldmatrix.sync.aligned.m8n8.x4.shared.b16 {%0,%1,%2,%3}, [%4];"
                 : "=r"(r0), "=r"(r1), "=r"(r2), "=r"(r3) : "r"(a));
}
__device__ __forceinline__ void mma16816(float* c, uint32_t a0, uint32_t a1,
                                         uint32_t a2, uint32_t a3,
                                         uint32_t b0, uint32_t b1) {
    asm volatile("mma.sync.aligned.m16n8k16.row.col.f32.f16.f16.f32 "
                 "{%0,%1,%2,%3}, {%4,%5,%6,%7}, {%8,%9}, {%0,%1,%2,%3};"
                 : "+f"(c[0]), "+f"(c[1]), "+f"(c[2]), "+f"(c[3])
                 : "r"(a0), "r"(a1), "r"(a2), "r"(a3), "r"(b0), "r"(b1));
}
__device__ __forceinline__ uint32_t packh2(float a, float b) {
    __half2 h = __floats2half2_rn(a, b);
    return *(uint32_t*)&h;
}

// ---------------------------------------------------------------------------
// dtype detection + combined biases (merged, one launch)
// ---------------------------------------------------------------------------
__global__ void setup_kernel(const int* __restrict__ iw, const int* __restrict__ lw,
                             const float* __restrict__ W_in, const float* __restrict__ b_in,
                             const float* __restrict__ bq, const float* __restrict__ bk,
                             const float* __restrict__ bv, const float* __restrict__ Wout,
                             const float* __restrict__ bo, const float* __restrict__ bout,
                             float* __restrict__ beff, float* __restrict__ bfinal) {
    int i = blockIdx.x * blockDim.x + threadIdx.x;
    if (i == QKV_DIM + OUTPUT_DIM) {
        int oi = 0, ol = 0;
        for (int k = 0; k < 256; k++) oi |= iw[2 * k + 1];
        for (int k = 0; k < 256; k++) ol |= lw[2 * k + 1];
        g_idx_is64 = (oi == 0) ? 1 : 0;
        g_len_is64 = (ol == 0) ? 1 : 0;
        return;
    }
    if (i < QKV_DIM) {
        const float* bs = (i < HIDDEN_DIM) ? bq : (i < 2 * HIDDEN_DIM ? bk : bv);
        const float* w = W_in + (size_t)i * HIDDEN_DIM;
        float s = 0.f;
        for (int k = 0; k < HIDDEN_DIM; k++) s = fmaf(w[k], bs[k], s);
        beff[i] = s + b_in[i];
    } else if (i < QKV_DIM + OUTPUT_DIM) {
        int o = i - QKV_DIM;
        const float* w = Wout + (size_t)o * HIDDEN_DIM;
        float s = 0.f;
        for (int k = 0; k < HIDDEN_DIM; k++) s = fmaf(w[k], bo[k], s);
        bfinal[o] = s + bout[o];
    }
}

// ---------------------------------------------------------------------------
// SIMT tile GEMM body (128x128, 8x8/thread). Small split-K GEMMs.
// ---------------------------------------------------------------------------
__device__ __forceinline__ void sgemm_tile_nn(int Klen, int lda, int ldb, int ldc,
                                              const float* __restrict__ A,
                                              const float* __restrict__ B,
                                              float* __restrict__ C, int bm, int bn) {
    __shared__ float As[8][128];
    __shared__ float Bs[8][128];
    const int tid = threadIdx.x;
    const int tx = tid & 15, ty = tid >> 4;
    float acc[8][8];
#pragma unroll
    for (int i = 0; i < 8; i++)
#pragma unroll
        for (int j = 0; j < 8; j++) acc[i][j] = 0.f;

    const int arow = tid >> 1, ak = (tid & 1) * 4;
    const int bkr = tid >> 5, bnc = (tid & 31) * 4;

    for (int k0 = 0; k0 < Klen; k0 += 8) {
        float4 av = *(const float4*)(A + (size_t)(bm + arow) * lda + k0 + ak);
        As[ak + 0][arow] = av.x; As[ak + 1][arow] = av.y;
        As[ak + 2][arow] = av.z; As[ak + 3][arow] = av.w;
        float4 bv = *(const float4*)(B + (size_t)(k0 + bkr) * ldb + bn + bnc);
        *(float4*)&Bs[bkr][bnc] = bv;
        __syncthreads();
#pragma unroll
        for (int kk = 0; kk < 8; kk++) {
            float a[8], b[8];
            *(float4*)&a[0] = *(const float4*)&As[kk][ty * 8];
            *(float4*)&a[4] = *(const float4*)&As[kk][ty * 8 + 4];
            *(float4*)&b[0] = *(const float4*)&Bs[kk][tx * 8];
            *(float4*)&b[4] = *(const float4*)&Bs[kk][tx * 8 + 4];
#pragma unroll
            for (int i = 0; i < 8; i++)
#pragma unroll
                for (int j = 0; j < 8; j++) acc[i][j] = fmaf(a[i], b[j], acc[i][j]);
        }
        __syncthreads();
    }
#pragma unroll
    for (int i = 0; i < 8; i++) {
        int row = bm + ty * 8 + i;
#pragma unroll
        for (int j = 0; j < 8; j += 4) {
            int col = bn + tx * 8 + j;
            *(float4*)(C + (size_t)row * ldc + col) = *(float4*)&acc[i][j];
        }
    }
}

// Merged Weff + Wfinal partials in ONE launch.
__global__ void __launch_bounds__(256)
weights_part_kernel(const float* __restrict__ W_in, const float* __restrict__ Wq,
                    const float* __restrict__ Wk, const float* __restrict__ Wv,
                    const float* __restrict__ Wout, const float* __restrict__ Wo) {
    int z = blockIdx.z;
    if (z < 12) {
        int t = z >> 2, sl = z & 3;
        const float* Bt = (t == 0) ? Wq : (t == 1 ? Wk : Wv);
        const float* A = W_in + (size_t)t * HIDDEN_DIM * HIDDEN_DIM + sl * 128;
        const float* B = Bt + (size_t)sl * 128 * INPUT_DIM;
        float* C = g_WeffPart + (size_t)sl * QKV_DIM * INPUT_DIM +
                   (size_t)t * HIDDEN_DIM * INPUT_DIM;
        sgemm_tile_nn(128, HIDDEN_DIM, INPUT_DIM, INPUT_DIM, A, B, C,
                      blockIdx.y * 128, blockIdx.x * 128);
    } else {
        if (blockIdx.x >= HIDDEN_DIM / 128 || blockIdx.y >= OUTPUT_DIM / 128) return;
        int sl = z - 12;
        sgemm_tile_nn(128, HIDDEN_DIM, HIDDEN_DIM, HIDDEN_DIM,
                      Wout + sl * 128, Wo + (size_t)sl * 128 * HIDDEN_DIM,
                      g_WfinalPart + (size_t)sl * OUTPUT_DIM * HIDDEN_DIM,
                      blockIdx.y * 128, blockIdx.x * 128);
    }
}

// ---------------------------------------------------------------------------
// Merged reduction: Weff partials -> fp16 B; Wfinal partials -> fp16
// ---------------------------------------------------------------------------
#define N_WEFF4  ((size_t)QKV_DIM * INPUT_DIM / 4)     // 294912
#define N_WFIN4  ((size_t)OUTPUT_DIM * HIDDEN_DIM / 4) // 32768
__global__ void reduce_weights_kernel() {
    size_t i = (size_t)blockIdx.x * blockDim.x + threadIdx.x;
    if (i < N_WEFF4) {
        const size_t stride = (size_t)QKV_DIM * INPUT_DIM;
        float4 s = *(const float4*)(g_WeffPart + i * 4);
#pragma unroll
        for (int p = 1; p < SPLITK; p++) {
            float4 v = *(const float4*)(g_WeffPart + p * stride + i * 4);
            s.x += v.x; s.y += v.y; s.z += v.z; s.w += v.w;
        }
        uint2 h;
        h.x = packh2(s.x, s.y); h.y = packh2(s.z, s.w);
        *(uint2*)(g_Bhi + i * 4) = h;
    } else if (i < N_WEFF4 + N_WFIN4) {
        size_t j = i - N_WEFF4;
        const size_t stride = (size_t)OUTPUT_DIM * HIDDEN_DIM;
        float4 s = *(const float4*)(g_WfinalPart + j * 4);
#pragma unroll
        for (int p = 1; p < SPLITK; p++) {
            float4 v = *(const float4*)(g_WfinalPart + p * stride + j * 4);
            s.x += v.x; s.y += v.y; s.z += v.z; s.w += v.w;
        }
        uint2 h;
        h.x = packh2(s.x, s.y); h.y = packh2(s.z, s.w);
        *(uint2*)(g_Wfinalh + j * 4) = h;
    }
}

// ---------------------------------------------------------------------------
// chunk fp32 -> fp16 (rows >= NUM_CHUNKS zero-padded to M_PAD)
// ---------------------------------------------------------------------------
__global__ void convert_chunk_kernel(const float* __restrict__ x) {
    size_t i = (size_t)blockIdx.x * blockDim.x + threadIdx.x;
    const size_t n8 = (size_t)M_PAD * INPUT_DIM / 8;
    if (i >= n8) return;
    uint4 out = make_uint4(0, 0, 0, 0);
    if (i * 8 < (size_t)NUM_CHUNKS * INPUT_DIM) {
        float4 v0 = *(const float4*)(x + i * 8);
        float4 v1 = *(const float4*)(x + i * 8 + 4);
        out.x = packh2(v0.x, v0.y); out.y = packh2(v0.z, v0.w);
        out.z = packh2(v1.x, v1.y); out.w = packh2(v1.z, v1.w);
    }
    *(uint4*)(g_Ahi + i * 8) = out;
}

// ---------------------------------------------------------------------------
// QKV GEMM via mma.sync fp16 (R11-proven 8-warp config). fp16 out.
// ---------------------------------------------------------------------------
__global__ void __launch_bounds__(256, 2)
qkv_mma_kernel(const float* __restrict__ beff, __half* __restrict__ C) {
    extern __shared__ __align__(128) char smem[];
    const uint32_t sb = smem_u32(smem);
    const int tid = threadIdx.x, lane = tid & 31, wid = tid >> 5;
    const int bm = blockIdx.y * 128, bn = blockIdx.x * 128;
    const int wm = (wid & 1) * 64, wn = (wid >> 1) * 32;

    float c[4][4][4];
#pragma unroll
    for (int mt = 0; mt < 4; mt++)
#pragma unroll
        for (int nt = 0; nt < 4; nt++)
#pragma unroll
            for (int r = 0; r < 4; r++) c[mt][nt][r] = 0.f;

    const uint32_t sw   = (uint32_t)((lane & 7) << 4);
    const int arow = wm + (lane & 15);
    const uint32_t ahi  = (uint32_t)(((lane >> 4) & 1) * 16);
    const int brow = wn + (lane & 7) + ((lane >> 4) & 1) * 8;
    const uint32_t bhi  = (uint32_t)(((lane >> 3) & 1) * 16);

    auto issue = [&](int chunk) {
        int st = chunk % 3;
        int ko = chunk * CHUNK_K;
        uint32_t base = sb + st * STAGE_B;
#pragma unroll
        for (int i = 0; i < 8; i++) {
            int u = tid + 256 * i;
            int row = (u >> 3) & 127;
            int c16 = u & 7;
            bool isB = u >= 1024;
            uint32_t dst = base + (isB ? TILE_BYTES : 0) + row * 128 +
                           ((uint32_t)(c16 * 16) ^ (uint32_t)((row & 7) << 4));
            const __half* src =
                isB ? g_Bhi + (size_t)(bn + row) * INPUT_DIM + ko + c16 * 8
                    : g_Ahi + (size_t)(bm + row) * INPUT_DIM + ko + c16 * 8;
            cp16(dst, src);
        }
        cp_commit();
    };

    issue(0);
    issue(1);

    for (int i = 0; i < NCHUNKS; i++) {
        cp_wait<1>();
        __syncthreads();
        if (i + 2 < NCHUNKS) issue(i + 2);
        else cp_commit();
        uint32_t sa = sb + (i % 3) * STAGE_B;
        uint32_t sB = sa + TILE_BYTES;
#pragma unroll
        for (int kf = 0; kf < 4; kf++) {
            uint32_t a[4][4], b[2][4];
#pragma unroll
            for (int mt = 0; mt < 4; mt++)
                ldsm4(a[mt][0], a[mt][1], a[mt][2], a[mt][3],
                      sa + (uint32_t)(arow + mt * 16) * 128 +
                          (((uint32_t)(kf * 32) + ahi) ^ sw));
#pragma unroll
            for (int bt = 0; bt < 2; bt++)
                ldsm4(b[bt][0], b[bt][1], b[bt][2], b[bt][3],
                      sB + (uint32_t)(brow + bt * 16) * 128 +
                          (((uint32_t)(kf * 32) + bhi) ^ sw));
#pragma unroll
            for (int mt = 0; mt < 4; mt++)
#pragma unroll
                for (int nt = 0; nt < 4; nt++)
                    mma16816(c[mt][nt], a[mt][0], a[mt][1], a[mt][2], a[mt][3],
                             b[nt >> 1][(nt & 1) * 2], b[nt >> 1][(nt & 1) * 2 + 1]);
        }
    }

    const int rr = bm + wm + (lane >> 2);
    const int cc = bn + wn + (lane & 3) * 2;
#pragma unroll
    for (int mt = 0; mt < 4; mt++) {
#pragma unroll
        for (int nt = 0; nt < 4; nt++) {
            int col = cc + nt * 8;
            float b0 = beff[col], b1 = beff[col + 1];
            int row = rr + mt * 16;
            if (row < NUM_CHUNKS) {
                uint32_t v = packh2(c[mt][nt][0] + b0, c[mt][nt][1] + b1);
                *(uint32_t*)(C + (size_t)row * QKV_DIM + col) = v;
            }
            if (row + 8 < NUM_CHUNKS) {
                uint32_t v = packh2(c[mt][nt][2] + b0, c[mt][nt][3] + b1);
                *(uint32_t*)(C + (size_t)(row + 8) * QKV_DIM + col) = v;
            }
        }
    }
}

// ---------------------------------------------------------------------------
// Final projection via mma.sync fp16 (R12-proven):
// out[2048,256] = pooled[2048,512](fp16) @ Wfinalh[256,512]^T + bfinal
// ---------------------------------------------------------------------------
__global__ void __launch_bounds__(256, 2)
out_mma_kernel(const float* __restrict__ bfinal, float* __restrict__ C) {
    extern __shared__ __align__(128) char smem[];
    const uint32_t sb = smem_u32(smem);
    const int tid = threadIdx.x, lane = tid & 31, wid = tid >> 5;
    const int bm = blockIdx.y * 128, bn = blockIdx.x * 128;
    const int wm = (wid & 1) * 64, wn = (wid >> 1) * 32;

    float c[4][4][4];
#pragma unroll
    for (int mt = 0; mt < 4; mt++)
#pragma unroll
        for (int nt = 0; nt < 4; nt++)
#pragma unroll
            for (int r = 0; r < 4; r++) c[mt][nt][r] = 0.f;

    const uint32_t sw   = (uint32_t)((lane & 7) << 4);
    const int arow = wm + (lane & 15);
    const uint32_t ahi  = (uint32_t)(((lane >> 4) & 1) * 16);
    const int brow = wn + (lane & 7) + ((lane >> 4) & 1) * 8;
    const uint32_t bhi  = (uint32_t)(((lane >> 3) & 1) * 16);

    auto issue = [&](int chunk) {
        int st = chunk % 3;
        int ko = chunk * CHUNK_K;
        uint32_t base = sb + st * STAGE_B;
#pragma unroll
        for (int i = 0; i < 8; i++) {
            int u = tid + 256 * i;
            int row = (u >> 3) & 127;
            int c16 = u & 7;
            bool isB = u >= 1024;
            uint32_t dst = base + (isB ? TILE_BYTES : 0) + row * 128 +
                           ((uint32_t)(c16 * 16) ^ (uint32_t)((row & 7) << 4));
            const __half* src =
                isB ? g_Wfinalh + (size_t)(bn + row) * HIDDEN_DIM + ko + c16 * 8
                    : g_pooled + (size_t)(bm + row) * HIDDEN_DIM + ko + c16 * 8;
            cp16(dst, src);
        }
        cp_commit();
    };

    issue(0);
    issue(1);

    for (int i = 0; i < NCHUNKS_O; i++) {
        cp_wait<1>();
        __syncthreads();
        if (i + 2 < NCHUNKS_O) issue(i + 2);
        else cp_commit();
        uint32_t sa = sb + (i % 3) * STAGE_B;
        uint32_t sB = sa + TILE_BYTES;
#pragma unroll
        for (int kf = 0; kf < 4; kf++) {
            uint32_t a[4][4], b[2][4];
#pragma unroll
            for (int mt = 0; mt < 4; mt++)
                ldsm4(a[mt][0], a[mt][1], a[mt][2], a[mt][3],
                      sa + (uint32_t)(arow + mt * 16) * 128 +
                          (((uint32_t)(kf * 32) + ahi) ^ sw));
#pragma unroll
            for (int bt = 0; bt < 2; bt++)
                ldsm4(b[bt][0], b[bt][1], b[bt][2], b[bt][3],
                      sB + (uint32_t)(brow + bt * 16) * 128 +
                          (((uint32_t)(kf * 32) + bhi) ^ sw));
#pragma unroll
            for (int mt = 0; mt < 4; mt++)
#pragma unroll
                for (int nt = 0; nt < 4; nt++)
                    mma16816(c[mt][nt], a[mt][0], a[mt][1], a[mt][2], a[mt][3],
                             b[nt >> 1][(nt & 1) * 2], b[nt >> 1][(nt & 1) * 2 + 1]);
        }
    }

    const int rr = bm + wm + (lane >> 2);
    const int cc = bn + wn + (lane & 3) * 2;
#pragma unroll
    for (int mt = 0; mt < 4; mt++) {
#pragma unroll
        for (int nt = 0; nt < 4; nt++) {
            int col = cc + nt * 8;
            float b0 = bfinal[col], b1 = bfinal[col + 1];
            int row = rr + mt * 16;
            float2 v0 = make_float2(c[mt][nt][0] + b0, c[mt][nt][1] + b1);
            *(float2*)(C + (size_t)row * OUTPUT_DIM + col) = v0;
            float2 v1 = make_float2(c[mt][nt][2] + b0, c[mt][nt][3] + b1);
            *(float2*)(C + (size_t)(row + 8) * OUTPUT_DIM + col) = v1;
        }
    }
}

// ---------------------------------------------------------------------------
// Attention + masked mean pool: 128 threads, 8 CTAs/SM (R15-proven), plus
// V prefetched via cp.async into the dead Q region, overlapping phases 2-3.
// ---------------------------------------------------------------------------
#define AT_SQ    0        // 8192: Q fp16 (reused as V tile after scores)
#define AT_SK    8192     // 8192: K fp16
#define AT_PS    16384    // 64*72*2 = 9216: probs fp16 (row stride 72 halfs)
#define AT_WS    25600    // 64*4: wsum
#define AT_PART  25856    // 2*64*4: partial pooled
#define AT_RIDX  26368    // 64*4: gathered indices
#define AT_TOTAL 26624

__global__ void __launch_bounds__(128)
attn_pool_kernel(const __half* __restrict__ QKV, const void* __restrict__ cell_idx,
                 const void* __restrict__ cell_len, __half* __restrict__ pooled) {
    __shared__ __align__(128) char sm[AT_TOTAL];
    const uint32_t sb = smem_u32(sm);
    __half* psh  = (__half*)(sm + AT_PS);    // [64][72]
    __half* vsh  = (__half*)(sm + AT_SQ);    // [64][64] after phase 2 (unswizzled)
    float* wsum = (float*)(sm + AT_WS);
    float* part = (float*)(sm + AT_PART);    // [2][64]
    int*   ridx = (int*)(sm + AT_RIDX);

    const int c = blockIdx.x, h = blockIdx.y, tid = threadIdx.x;
    const int lane = tid & 31, wid = tid >> 5;
    const int hoff = h * HEAD_DIM;
    const int sI = g_idx_is64 ? 2 : 1;
    const int sL = g_len_is64 ? 2 : 1;
    const int* idx32 = (const int*)cell_idx;
    const int* len32 = (const int*)cell_len;

    int len = len32[(size_t)c * sL];
    int Leff = len < 1 ? 1 : (len > 64 ? 64 : len);
    if (tid < 64) ridx[tid] = idx32[((size_t)c * MAX_LEN + tid) * sI];
    __syncthreads();

    // Phase 1: gather Q,K fp16 via cp.async (zero rows >= Leff).
#pragma unroll
    for (int it = 0; it < 8; it++) {
        int u = tid + 128 * it;
        int mat = u >> 9;                  // 0 = Q, 1 = K
        int idx = u & 511;
        int row = idx >> 3, c16 = idx & 7;
        uint32_t dst = sb + (mat ? AT_SK : AT_SQ) + row * 128 +
                       ((uint32_t)(c16 * 16) ^ (uint32_t)((row & 7) << 4));
        if (row < Leff) {
            const __half* src = QKV + (size_t)ridx[row] * QKV_DIM + hoff +
                                (mat ? HIDDEN_DIM : 0) + c16 * 8;
            cp16(dst, src);
        } else {
            asm volatile("st.shared.v4.b32 [%0], {%1,%1,%1,%1};"
                         :: "r"(dst), "r"(0u) : "memory");
        }
    }
    cp_commit();
    cp_wait<0>();
    __syncthreads();

    // Phase 2a: ALL 4 warps run the score mma loop (Q,K smem reads)
    float cfr[8][4];
#pragma unroll
    for (int nt = 0; nt < 8; nt++)
#pragma unroll
        for (int r = 0; r < 4; r++) cfr[nt][r] = 0.f;
    {
        const uint32_t swl = (uint32_t)((lane & 7) << 4);
        const uint32_t abase = sb + AT_SQ + (uint32_t)(16 * wid + (lane & 15)) * 128;
        const uint32_t ahi = (uint32_t)(((lane >> 4) & 1) * 16);
        const int brow = (lane & 7) + ((lane >> 4) & 1) * 8;
        const uint32_t bhi = (uint32_t)(((lane >> 3) & 1) * 16);

#pragma unroll
        for (int kf = 0; kf < 4; kf++) {
            uint32_t a0, a1, a2, a3, b[4][4];
            ldsm4(a0, a1, a2, a3, abase + (((uint32_t)(kf * 32) + ahi) ^ swl));
#pragma unroll
            for (int bt = 0; bt < 4; bt++)
                ldsm4(b[bt][0], b[bt][1], b[bt][2], b[bt][3],
                      sb + AT_SK + (uint32_t)(bt * 16 + brow) * 128 +
                          (((uint32_t)(kf * 32) + bhi) ^ swl));
#pragma unroll
            for (int nt = 0; nt < 8; nt++)
                mma16816(cfr[nt], a0, a1, a2, a3,
                         b[nt >> 1][(nt & 1) * 2], b[nt >> 1][(nt & 1) * 2 + 1]);
        }
    }
    __syncthreads();   // all warps done reading Q tile -> safe to overwrite with V

    // Phase 2b: issue V gather into old Q region (64 rows x 128B, unswizzled),
    // overlapping with softmax + prob writes + column mean below.
#pragma unroll
    for (int it = 0; it < 4; it++) {
        int u = tid + 128 * it;            // 512 units
        int row = u >> 3, c16 = u & 7;
        uint32_t dst = sb + AT_SQ + row * 128 + c16 * 16;
        if (row < Leff) {
            cp16(dst, QKV + (size_t)ridx[row] * QKV_DIM + 2 * HIDDEN_DIM + hoff + c16 * 8);
        } else {
            asm volatile("st.shared.v4.b32 [%0], {%1,%1,%1,%1};"
                         :: "r"(dst), "r"(0u) : "memory");
        }
    }
    cp_commit();

    // Phase 2c: softmax on fragments, write probs fp16
    {
        float m0 = -1e30f, m1 = -1e30f;
#pragma unroll
        for (int nt = 0; nt < 8; nt++)
#pragma unroll
            for (int rg = 0; rg < 2; rg++) {
                int col = nt * 8 + (lane & 3) * 2 + rg;
                if (col < Leff) {
                    m0 = fmaxf(m0, cfr[nt][rg] * 0.125f);
                    m1 = fmaxf(m1, cfr[nt][2 + rg] * 0.125f);
                }
            }
        m0 = fmaxf(m0, __shfl_xor_sync(0xffffffffu, m0, 1));
        m0 = fmaxf(m0, __shfl_xor_sync(0xffffffffu, m0, 2));
        m1 = fmaxf(m1, __shfl_xor_sync(0xffffffffu, m1, 1));
        m1 = fmaxf(m1, __shfl_xor_sync(0xffffffffu, m1, 2));

        float s0 = 0.f, s1 = 0.f;
#pragma unroll
        for (int nt = 0; nt < 8; nt++)
#pragma unroll
            for (int rg = 0; rg < 2; rg++) {
                int col = nt * 8 + (lane & 3) * 2 + rg;
                float e0 = (col < Leff) ? __expf(cfr[nt][rg] * 0.125f - m0) : 0.f;
                float e1 = (col < Leff) ? __expf(cfr[nt][2 + rg] * 0.125f - m1) : 0.f;
                cfr[nt][rg] = e0;
                cfr[nt][2 + rg] = e1;
                s0 += e0; s1 += e1;
            }
        s0 += __shfl_xor_sync(0xffffffffu, s0, 1);
        s0 += __shfl_xor_sync(0xffffffffu, s0, 2);
        s1 += __shfl_xor_sync(0xffffffffu, s1, 1);
        s1 += __shfl_xor_sync(0xffffffffu, s1, 2);
        float i0 = 1.f / s0, i1 = 1.f / s1;

        int row0 = 16 * wid + (lane >> 2);
#pragma unroll
        for (int nt = 0; nt < 8; nt++)
#pragma unroll
            for (int rg = 0; rg < 2; rg++) {
                int col = nt * 8 + (lane & 3) * 2 + rg;
                psh[row0 * 72 + col] = __float2half(cfr[nt][rg] * i0);
                psh[(row0 + 8) * 72 + col] = __float2half(cfr[nt][2 + rg] * i1);
            }
    }
    __syncthreads();

    // Phase 3: column mean over valid query rows (V loads still in flight)
    if (tid < 64) {
        float s = 0.f;
        for (int ll = 0; ll < Leff; ll++) s += __half2float(psh[ll * 72 + tid]);
        wsum[tid] = s / (float)Leff;
    }
    cp_wait<0>();      // V tile resident
    __syncthreads();

    // Phase 4: pooled[d] = sum_{m<Leff} wsum[m] * V[m][d] from smem
    {
        int pt = tid >> 6, d = tid & 63;
        float acc = 0.f;
        for (int m = pt; m < Leff; m += 2)
            acc = fmaf(wsum[m], __half2float(vsh[m * 64 + d]), acc);
        part[pt * 64 + d] = acc;
    }
    __syncthreads();
    if (tid < 64)
        pooled[(size_t)c * HIDDEN_DIM + hoff + tid] =
            __float2half(part[tid] + part[64 + tid]);
}

// ---------------------------------------------------------------------------
// Launch (single stream, R15 ordering)
// ---------------------------------------------------------------------------
extern "C" void kernel_launch(void* const* d_in, const int* in_sizes, int n_in,
                              void* d_out, int out_size) {
    const float* chunk = (const float*)d_in[0];
    const float* Wq   = (const float*)d_in[1];
    const float* bq   = (const float*)d_in[2];
    const float* Wk   = (const float*)d_in[3];
    const float* bk   = (const float*)d_in[4];
    const float* Wv   = (const float*)d_in[5];
    const float* bv   = (const float*)d_in[6];
    const float* W_in = (const float*)d_in[7];
    const float* b_in = (const float*)d_in[8];
    const float* Wo   = (const float*)d_in[9];
    const float* bo   = (const float*)d_in[10];
    const float* Wout = (const float*)d_in[11];
    const float* bout = (const float*)d_in[12];
    const void*  cidx = d_in[13];
    const void*  clen = d_in[14];
    float* out = (float*)d_out;

    __half *pQKV, *pPooled;
    float *pbeff, *pbfinal;
    cudaGetSymbolAddress((void**)&pQKV, g_QKV);
    cudaGetSymbolAddress((void**)&pPooled, g_pooled);
    cudaGetSymbolAddress((void**)&pbeff, g_beff);
    cudaGetSymbolAddress((void**)&pbfinal, g_bfinal);

    static bool attr_set = false;
    if (!attr_set) {
        cudaFuncSetAttribute(qkv_mma_kernel, cudaFuncAttributeMaxDynamicSharedMemorySize,
                             SMEM_MMA);
        cudaFuncSetAttribute(out_mma_kernel, cudaFuncAttributeMaxDynamicSharedMemorySize,
                             SMEM_MMA);
        attr_set = true;
    }

    // 0+1) dtype detection + combined biases (merged)
    setup_kernel<<<(QKV_DIM + OUTPUT_DIM + 1 + 255) / 256, 256>>>(
        (const int*)cidx, (const int*)clen,
        W_in, b_in, bq, bk, bv, Wout, bo, bout, pbeff, pbfinal);

    // 2) merged small GEMMs (Weff + Wfinal) + merged reduce (emit fp16)
    weights_part_kernel<<<dim3(INPUT_DIM / 128, HIDDEN_DIM / 128, 16), 256>>>(
        W_in, Wq, Wk, Wv, Wout, Wo);
    reduce_weights_kernel<<<(unsigned)((N_WEFF4 + N_WFIN4 + 255) / 256), 256>>>();

    // 3) chunk -> fp16
    convert_chunk_kernel<<<((size_t)M_PAD * INPUT_DIM / 8 + 255) / 256, 256>>>(chunk);

    // 4) QKV projection (8-warp R11 config, fp16 output)
    qkv_mma_kernel<<<dim3(QKV_DIM / 128, M_PAD / 128), 256, SMEM_MMA>>>(pbeff, pQKV);

    // 5) fused attention + masked mean pool (V prefetch overlapped)
    attn_pool_kernel<<<dim3(NUM_CELLS, NUM_HEADS), 128>>>(pQKV, cidx, clen, pPooled);

    // 6) final projection via mma
    out_mma_kernel<<<dim3(OUTPUT_DIM / 128, NUM_CELLS / 128), 256, SMEM_MMA>>>(pbfinal, out);
}

// round 17
// speedup vs baseline: 1.1986x; 1.0031x over previous
#include <cuda_runtime.h>
#include <cuda_fp16.h>
#include <cuda_bf16.h>
#include <math.h>
#include <stdint.h>

// ---------------------------------------------------------------------------
// Problem constants
// ---------------------------------------------------------------------------
#define NUM_HEADS   8
#define NUM_CHUNKS  50000
#define INPUT_DIM   768
#define HIDDEN_DIM  512
#define OUTPUT_DIM  256
#define NUM_CELLS   2048
#define MAX_LEN     64
#define HEAD_DIM    64
#define QKV_DIM     1536
#define M_PAD       50048              // 391 * 128
#define SPLITK      4

// mma GEMM geometry (k-chunk 64, swizzled smem, 3 stages, 2 CTA/SM)
#define CHUNK_K     64
#define NCHUNKS     12                 // single fp16 pass: 768/64
#define NCHUNKS_O   8                  // final projection: 512/64
#define TILE_BYTES  (128 * 128)        // 16384 (128 rows x 128B swizzled)
#define STAGE_B     (2 * TILE_BYTES)   // 32768
#define SMEM_MMA    (3 * STAGE_B)      // 98304

// convert-as-z-slices geometry for the merged weights+convert launch
#define CONV_Z      56                 // z slices 16..71 -> 56*24 = 1344 blocks
#define N8_CONV     ((size_t)M_PAD * INPUT_DIM / 8)   // 4,804,608 uint4 groups

// ---------------------------------------------------------------------------
// Device-global scratch (allocation-free contract)
// ---------------------------------------------------------------------------
__device__ __align__(1024) __half g_Ahi[(size_t)M_PAD * INPUT_DIM];
__device__ __align__(1024) __half g_Bhi[QKV_DIM * INPUT_DIM];
__device__ __align__(1024) __half g_QKV[(size_t)NUM_CHUNKS * QKV_DIM];
__device__ __align__(1024) __half g_pooled[NUM_CELLS * HIDDEN_DIM];
__device__ __align__(1024) __half g_Wfinalh[OUTPUT_DIM * HIDDEN_DIM];
__device__ __align__(256) float g_beff[QKV_DIM];
__device__ __align__(256) float g_bfinal[OUTPUT_DIM];
__device__ __align__(256) float g_WeffPart[SPLITK * QKV_DIM * INPUT_DIM];
__device__ __align__(256) float g_WfinalPart[SPLITK * OUTPUT_DIM * HIDDEN_DIM];
__device__ int g_idx_is64;
__device__ int g_len_is64;

// ---------------------------------------------------------------------------
// PTX helpers (plain-sm_80-level: safe for non-'a' ptx target)
// ---------------------------------------------------------------------------
__device__ __forceinline__ uint32_t smem_u32(const void* p) {
    uint32_t a;
    asm("{ .reg .u64 t; cvta.to.shared.u64 t, %1; cvt.u32.u64 %0, t; }"
        : "=r"(a) : "l"(p));
    return a;
}
__device__ __forceinline__ void cp16(uint32_t d, const void* s) {
    asm volatile("cp.async.cg.shared.global [%0], [%1], 16;" :: "r"(d), "l"(s));
}
__device__ __forceinline__ void cp_commit() {
    asm volatile("cp.async.commit_group;" ::: "memory");
}
template <int N>
__device__ __forceinline__ void cp_wait() {
    asm volatile("cp.async.wait_group %0;" :: "n"(N) : "memory");
}
__device__ __forceinline__ void ldsm4(uint32_t& r0, uint32_t& r1, uint32_t& r2,
                                      uint32_t& r3, uint32_t a) {
    asm volatile("ldmatrix.sync.aligned.m8n8.x4.shared.b16 {%0,%1,%2,%3}, [%4];"
                 : "=r"(r0), "=r"(r1), "=r"(r2), "=r"(r3) : "r"(a));
}
__device__ __forceinline__ void mma16816(float* c, uint32_t a0, uint32_t a1,
                                         uint32_t a2, uint32_t a3,
                                         uint32_t b0, uint32_t b1) {
    asm volatile("mma.sync.aligned.m16n8k16.row.col.f32.f16.f16.f32 "
                 "{%0,%1,%2,%3}, {%4,%5,%6,%7}, {%8,%9}, {%0,%1,%2,%3};"
                 : "+f"(c[0]), "+f"(c[1]), "+f"(c[2]), "+f"(c[3])
                 : "r"(a0), "r"(a1), "r"(a2), "r"(a3), "r"(b0), "r"(b1));
}
__device__ __forceinline__ uint32_t packh2(float a, float b) {
    __half2 h = __floats2half2_rn(a, b);
    return *(uint32_t*)&h;
}

// ---------------------------------------------------------------------------
// dtype detection + combined biases (merged, one launch)
// ---------------------------------------------------------------------------
__global__ void setup_kernel(const int* __restrict__ iw, const int* __restrict__ lw,
                             const float* __restrict__ W_in, const float* __restrict__ b_in,
                             const float* __restrict__ bq, const float* __restrict__ bk,
                             const float* __restrict__ bv, const float* __restrict__ Wout,
                             const float* __restrict__ bo, const float* __restrict__ bout,
                             float* __restrict__ beff, float* __restrict__ bfinal) {
    int i = blockIdx.x * blockDim.x + threadIdx.x;
    if (i == QKV_DIM + OUTPUT_DIM) {
        int oi = 0, ol = 0;
        for (int k = 0; k < 256; k++) oi |= iw[2 * k + 1];
        for (int k = 0; k < 256; k++) ol |= lw[2 * k + 1];
        g_idx_is64 = (oi == 0) ? 1 : 0;
        g_len_is64 = (ol == 0) ? 1 : 0;
        return;
    }
    if (i < QKV_DIM) {
        const float* bs = (i < HIDDEN_DIM) ? bq : (i < 2 * HIDDEN_DIM ? bk : bv);
        const float* w = W_in + (size_t)i * HIDDEN_DIM;
        float s = 0.f;
        for (int k = 0; k < HIDDEN_DIM; k++) s = fmaf(w[k], bs[k], s);
        beff[i] = s + b_in[i];
    } else if (i < QKV_DIM + OUTPUT_DIM) {
        int o = i - QKV_DIM;
        const float* w = Wout + (size_t)o * HIDDEN_DIM;
        float s = 0.f;
        for (int k = 0; k < HIDDEN_DIM; k++) s = fmaf(w[k], bo[k], s);
        bfinal[o] = s + bout[o];
    }
}

// ---------------------------------------------------------------------------
// SIMT tile GEMM body (128x128, 8x8/thread). Small split-K GEMMs.
// ---------------------------------------------------------------------------
__device__ __forceinline__ void sgemm_tile_nn(int Klen, int lda, int ldb, int ldc,
                                              const float* __restrict__ A,
                                              const float* __restrict__ B,
                                              float* __restrict__ C, int bm, int bn) {
    __shared__ float As[8][128];
    __shared__ float Bs[8][128];
    const int tid = threadIdx.x;
    const int tx = tid & 15, ty = tid >> 4;
    float acc[8][8];
#pragma unroll
    for (int i = 0; i < 8; i++)
#pragma unroll
        for (int j = 0; j < 8; j++) acc[i][j] = 0.f;

    const int arow = tid >> 1, ak = (tid & 1) * 4;
    const int bkr = tid >> 5, bnc = (tid & 31) * 4;

    for (int k0 = 0; k0 < Klen; k0 += 8) {
        float4 av = *(const float4*)(A + (size_t)(bm + arow) * lda + k0 + ak);
        As[ak + 0][arow] = av.x; As[ak + 1][arow] = av.y;
        As[ak + 2][arow] = av.z; As[ak + 3][arow] = av.w;
        float4 bv = *(const float4*)(B + (size_t)(k0 + bkr) * ldb + bn + bnc);
        *(float4*)&Bs[bkr][bnc] = bv;
        __syncthreads();
#pragma unroll
        for (int kk = 0; kk < 8; kk++) {
            float a[8], b[8];
            *(float4*)&a[0] = *(const float4*)&As[kk][ty * 8];
            *(float4*)&a[4] = *(const float4*)&As[kk][ty * 8 + 4];
            *(float4*)&b[0] = *(const float4*)&Bs[kk][tx * 8];
            *(float4*)&b[4] = *(const float4*)&Bs[kk][tx * 8 + 4];
#pragma unroll
            for (int i = 0; i < 8; i++)
#pragma unroll
                for (int j = 0; j < 8; j++) acc[i][j] = fmaf(a[i], b[j], acc[i][j]);
        }
        __syncthreads();
    }
#pragma unroll
    for (int i = 0; i < 8; i++) {
        int row = bm + ty * 8 + i;
#pragma unroll
        for (int j = 0; j < 8; j += 4) {
            int col = bn + tx * 8 + j;
            *(float4*)(C + (size_t)row * ldc + col) = *(float4*)&acc[i][j];
        }
    }
}

// Merged Weff + Wfinal partials + chunk fp32->fp16 convert, ONE launch.
// z in [0,12): Weff; z in [12,16): Wfinal (guarded); z in [16,72): convert.
__global__ void __launch_bounds__(256)
weights_part_kernel(const float* __restrict__ W_in, const float* __restrict__ Wq,
                    const float* __restrict__ Wk, const float* __restrict__ Wv,
                    const float* __restrict__ Wout, const float* __restrict__ Wo,
                    const float* __restrict__ chunk) {
    int z = blockIdx.z;
    if (z >= 16) {
        // convert slice (grid-stride over uint4-of-half groups)
        int blk = (z - 16) * 24 + blockIdx.y * 6 + blockIdx.x;
        const size_t stride = (size_t)CONV_Z * 24 * 256;
        const size_t limit = (size_t)NUM_CHUNKS * INPUT_DIM;
        for (size_t i = (size_t)blk * 256 + threadIdx.x; i < N8_CONV; i += stride) {
            uint4 out = make_uint4(0, 0, 0, 0);
            if (i * 8 < limit) {
                float4 v0 = *(const float4*)(chunk + i * 8);
                float4 v1 = *(const float4*)(chunk + i * 8 + 4);
                out.x = packh2(v0.x, v0.y); out.y = packh2(v0.z, v0.w);
                out.z = packh2(v1.x, v1.y); out.w = packh2(v1.z, v1.w);
            }
            *(uint4*)(g_Ahi + i * 8) = out;
        }
        return;
    }
    if (z < 12) {
        int t = z >> 2, sl = z & 3;
        const float* Bt = (t == 0) ? Wq : (t == 1 ? Wk : Wv);
        const float* A = W_in + (size_t)t * HIDDEN_DIM * HIDDEN_DIM + sl * 128;
        const float* B = Bt + (size_t)sl * 128 * INPUT_DIM;
        float* C = g_WeffPart + (size_t)sl * QKV_DIM * INPUT_DIM +
                   (size_t)t * HIDDEN_DIM * INPUT_DIM;
        sgemm_tile_nn(128, HIDDEN_DIM, INPUT_DIM, INPUT_DIM, A, B, C,
                      blockIdx.y * 128, blockIdx.x * 128);
    } else {
        if (blockIdx.x >= HIDDEN_DIM / 128 || blockIdx.y >= OUTPUT_DIM / 128) return;
        int sl = z - 12;
        sgemm_tile_nn(128, HIDDEN_DIM, HIDDEN_DIM, HIDDEN_DIM,
                      Wout + sl * 128, Wo + (size_t)sl * 128 * HIDDEN_DIM,
                      g_WfinalPart + (size_t)sl * OUTPUT_DIM * HIDDEN_DIM,
                      blockIdx.y * 128, blockIdx.x * 128);
    }
}

// ---------------------------------------------------------------------------
// Merged reduction: Weff partials -> fp16 B; Wfinal partials -> fp16
// ---------------------------------------------------------------------------
#define N_WEFF4  ((size_t)QKV_DIM * INPUT_DIM / 4)     // 294912
#define N_WFIN4  ((size_t)OUTPUT_DIM * HIDDEN_DIM / 4) // 32768
__global__ void reduce_weights_kernel() {
    size_t i = (size_t)blockIdx.x * blockDim.x + threadIdx.x;
    if (i < N_WEFF4) {
        const size_t stride = (size_t)QKV_DIM * INPUT_DIM;
        float4 s = *(const float4*)(g_WeffPart + i * 4);
#pragma unroll
        for (int p = 1; p < SPLITK; p++) {
            float4 v = *(const float4*)(g_WeffPart + p * stride + i * 4);
            s.x += v.x; s.y += v.y; s.z += v.z; s.w += v.w;
        }
        uint2 h;
        h.x = packh2(s.x, s.y); h.y = packh2(s.z, s.w);
        *(uint2*)(g_Bhi + i * 4) = h;
    } else if (i < N_WEFF4 + N_WFIN4) {
        size_t j = i - N_WEFF4;
        const size_t stride = (size_t)OUTPUT_DIM * HIDDEN_DIM;
        float4 s = *(const float4*)(g_WfinalPart + j * 4);
#pragma unroll
        for (int p = 1; p < SPLITK; p++) {
            float4 v = *(const float4*)(g_WfinalPart + p * stride + j * 4);
            s.x += v.x; s.y += v.y; s.z += v.z; s.w += v.w;
        }
        uint2 h;
        h.x = packh2(s.x, s.y); h.y = packh2(s.z, s.w);
        *(uint2*)(g_Wfinalh + j * 4) = h;
    }
}

// ---------------------------------------------------------------------------
// QKV GEMM via mma.sync fp16 (R11-proven 8-warp config). fp16 out.
// ---------------------------------------------------------------------------
__global__ void __launch_bounds__(256, 2)
qkv_mma_kernel(const float* __restrict__ beff, __half* __restrict__ C) {
    extern __shared__ __align__(128) char smem[];
    const uint32_t sb = smem_u32(smem);
    const int tid = threadIdx.x, lane = tid & 31, wid = tid >> 5;
    const int bm = blockIdx.y * 128, bn = blockIdx.x * 128;
    const int wm = (wid & 1) * 64, wn = (wid >> 1) * 32;

    float c[4][4][4];
#pragma unroll
    for (int mt = 0; mt < 4; mt++)
#pragma unroll
        for (int nt = 0; nt < 4; nt++)
#pragma unroll
            for (int r = 0; r < 4; r++) c[mt][nt][r] = 0.f;

    const uint32_t sw   = (uint32_t)((lane & 7) << 4);
    const int arow = wm + (lane & 15);
    const uint32_t ahi  = (uint32_t)(((lane >> 4) & 1) * 16);
    const int brow = wn + (lane & 7) + ((lane >> 4) & 1) * 8;
    const uint32_t bhi  = (uint32_t)(((lane >> 3) & 1) * 16);

    auto issue = [&](int chunk) {
        int st = chunk % 3;
        int ko = chunk * CHUNK_K;
        uint32_t base = sb + st * STAGE_B;
#pragma unroll
        for (int i = 0; i < 8; i++) {
            int u = tid + 256 * i;
            int row = (u >> 3) & 127;
            int c16 = u & 7;
            bool isB = u >= 1024;
            uint32_t dst = base + (isB ? TILE_BYTES : 0) + row * 128 +
                           ((uint32_t)(c16 * 16) ^ (uint32_t)((row & 7) << 4));
            const __half* src =
                isB ? g_Bhi + (size_t)(bn + row) * INPUT_DIM + ko + c16 * 8
                    : g_Ahi + (size_t)(bm + row) * INPUT_DIM + ko + c16 * 8;
            cp16(dst, src);
        }
        cp_commit();
    };

    issue(0);
    issue(1);

    for (int i = 0; i < NCHUNKS; i++) {
        cp_wait<1>();
        __syncthreads();
        if (i + 2 < NCHUNKS) issue(i + 2);
        else cp_commit();
        uint32_t sa = sb + (i % 3) * STAGE_B;
        uint32_t sB = sa + TILE_BYTES;
#pragma unroll
        for (int kf = 0; kf < 4; kf++) {
            uint32_t a[4][4], b[2][4];
#pragma unroll
            for (int mt = 0; mt < 4; mt++)
                ldsm4(a[mt][0], a[mt][1], a[mt][2], a[mt][3],
                      sa + (uint32_t)(arow + mt * 16) * 128 +
                          (((uint32_t)(kf * 32) + ahi) ^ sw));
#pragma unroll
            for (int bt = 0; bt < 2; bt++)
                ldsm4(b[bt][0], b[bt][1], b[bt][2], b[bt][3],
                      sB + (uint32_t)(brow + bt * 16) * 128 +
                          (((uint32_t)(kf * 32) + bhi) ^ sw));
#pragma unroll
            for (int mt = 0; mt < 4; mt++)
#pragma unroll
                for (int nt = 0; nt < 4; nt++)
                    mma16816(c[mt][nt], a[mt][0], a[mt][1], a[mt][2], a[mt][3],
                             b[nt >> 1][(nt & 1) * 2], b[nt >> 1][(nt & 1) * 2 + 1]);
        }
    }

    const int rr = bm + wm + (lane >> 2);
    const int cc = bn + wn + (lane & 3) * 2;
#pragma unroll
    for (int mt = 0; mt < 4; mt++) {
#pragma unroll
        for (int nt = 0; nt < 4; nt++) {
            int col = cc + nt * 8;
            float b0 = beff[col], b1 = beff[col + 1];
            int row = rr + mt * 16;
            if (row < NUM_CHUNKS) {
                uint32_t v = packh2(c[mt][nt][0] + b0, c[mt][nt][1] + b1);
                *(uint32_t*)(C + (size_t)row * QKV_DIM + col) = v;
            }
            if (row + 8 < NUM_CHUNKS) {
                uint32_t v = packh2(c[mt][nt][2] + b0, c[mt][nt][3] + b1);
                *(uint32_t*)(C + (size_t)(row + 8) * QKV_DIM + col) = v;
            }
        }
    }
}

// ---------------------------------------------------------------------------
// Final projection via mma.sync fp16 (R12-proven):
// out[2048,256] = pooled[2048,512](fp16) @ Wfinalh[256,512]^T + bfinal
// ---------------------------------------------------------------------------
__global__ void __launch_bounds__(256, 2)
out_mma_kernel(const float* __restrict__ bfinal, float* __restrict__ C) {
    extern __shared__ __align__(128) char smem[];
    const uint32_t sb = smem_u32(smem);
    const int tid = threadIdx.x, lane = tid & 31, wid = tid >> 5;
    const int bm = blockIdx.y * 128, bn = blockIdx.x * 128;
    const int wm = (wid & 1) * 64, wn = (wid >> 1) * 32;

    float c[4][4][4];
#pragma unroll
    for (int mt = 0; mt < 4; mt++)
#pragma unroll
        for (int nt = 0; nt < 4; nt++)
#pragma unroll
            for (int r = 0; r < 4; r++) c[mt][nt][r] = 0.f;

    const uint32_t sw   = (uint32_t)((lane & 7) << 4);
    const int arow = wm + (lane & 15);
    const uint32_t ahi  = (uint32_t)(((lane >> 4) & 1) * 16);
    const int brow = wn + (lane & 7) + ((lane >> 4) & 1) * 8;
    const uint32_t bhi  = (uint32_t)(((lane >> 3) & 1) * 16);

    auto issue = [&](int chunk) {
        int st = chunk % 3;
        int ko = chunk * CHUNK_K;
        uint32_t base = sb + st * STAGE_B;
#pragma unroll
        for (int i = 0; i < 8; i++) {
            int u = tid + 256 * i;
            int row = (u >> 3) & 127;
            int c16 = u & 7;
            bool isB = u >= 1024;
            uint32_t dst = base + (isB ? TILE_BYTES : 0) + row * 128 +
                           ((uint32_t)(c16 * 16) ^ (uint32_t)((row & 7) << 4));
            const __half* src =
                isB ? g_Wfinalh + (size_t)(bn + row) * HIDDEN_DIM + ko + c16 * 8
                    : g_pooled + (size_t)(bm + row) * HIDDEN_DIM + ko + c16 * 8;
            cp16(dst, src);
        }
        cp_commit();
    };

    issue(0);
    issue(1);

    for (int i = 0; i < NCHUNKS_O; i++) {
        cp_wait<1>();
        __syncthreads();
        if (i + 2 < NCHUNKS_O) issue(i + 2);
        else cp_commit();
        uint32_t sa = sb + (i % 3) * STAGE_B;
        uint32_t sB = sa + TILE_BYTES;
#pragma unroll
        for (int kf = 0; kf < 4; kf++) {
            uint32_t a[4][4], b[2][4];
#pragma unroll
            for (int mt = 0; mt < 4; mt++)
                ldsm4(a[mt][0], a[mt][1], a[mt][2], a[mt][3],
                      sa + (uint32_t)(arow + mt * 16) * 128 +
                          (((uint32_t)(kf * 32) + ahi) ^ sw));
#pragma unroll
            for (int bt = 0; bt < 2; bt++)
                ldsm4(b[bt][0], b[bt][1], b[bt][2], b[bt][3],
                      sB + (uint32_t)(brow + bt * 16) * 128 +
                          (((uint32_t)(kf * 32) + bhi) ^ sw));
#pragma unroll
            for (int mt = 0; mt < 4; mt++)
#pragma unroll
                for (int nt = 0; nt < 4; nt++)
                    mma16816(c[mt][nt], a[mt][0], a[mt][1], a[mt][2], a[mt][3],
                             b[nt >> 1][(nt & 1) * 2], b[nt >> 1][(nt & 1) * 2 + 1]);
        }
    }

    const int rr = bm + wm + (lane >> 2);
    const int cc = bn + wn + (lane & 3) * 2;
#pragma unroll
    for (int mt = 0; mt < 4; mt++) {
#pragma unroll
        for (int nt = 0; nt < 4; nt++) {
            int col = cc + nt * 8;
            float b0 = bfinal[col], b1 = bfinal[col + 1];
            int row = rr + mt * 16;
            float2 v0 = make_float2(c[mt][nt][0] + b0, c[mt][nt][1] + b1);
            *(float2*)(C + (size_t)row * OUTPUT_DIM + col) = v0;
            float2 v1 = make_float2(c[mt][nt][2] + b0, c[mt][nt][3] + b1);
            *(float2*)(C + (size_t)(row + 8) * OUTPUT_DIM + col) = v1;
        }
    }
}

// ---------------------------------------------------------------------------
// Attention + masked mean pool (R16-proven: 128 threads, 8 CTAs/SM,
// V prefetched via cp.async into the dead Q region)
// ---------------------------------------------------------------------------
#define AT_SQ    0        // 8192: Q fp16 (reused as V tile after scores)
#define AT_SK    8192     // 8192: K fp16
#define AT_PS    16384    // 64*72*2 = 9216: probs fp16 (row stride 72 halfs)
#define AT_WS    25600    // 64*4: wsum
#define AT_PART  25856    // 2*64*4: partial pooled
#define AT_RIDX  26368    // 64*4: gathered indices
#define AT_TOTAL 26624

__global__ void __launch_bounds__(128)
attn_pool_kernel(const __half* __restrict__ QKV, const void* __restrict__ cell_idx,
                 const void* __restrict__ cell_len, __half* __restrict__ pooled) {
    __shared__ __align__(128) char sm[AT_TOTAL];
    const uint32_t sb = smem_u32(sm);
    __half* psh  = (__half*)(sm + AT_PS);    // [64][72]
    __half* vsh  = (__half*)(sm + AT_SQ);    // [64][64] after phase 2 (unswizzled)
    float* wsum = (float*)(sm + AT_WS);
    float* part = (float*)(sm + AT_PART);    // [2][64]
    int*   ridx = (int*)(sm + AT_RIDX);

    const int c = blockIdx.x, h = blockIdx.y, tid = threadIdx.x;
    const int lane = tid & 31, wid = tid >> 5;
    const int hoff = h * HEAD_DIM;
    const int sI = g_idx_is64 ? 2 : 1;
    const int sL = g_len_is64 ? 2 : 1;
    const int* idx32 = (const int*)cell_idx;
    const int* len32 = (const int*)cell_len;

    int len = len32[(size_t)c * sL];
    int Leff = len < 1 ? 1 : (len > 64 ? 64 : len);
    if (tid < 64) ridx[tid] = idx32[((size_t)c * MAX_LEN + tid) * sI];
    __syncthreads();

    // Phase 1: gather Q,K fp16 via cp.async (zero rows >= Leff).
#pragma unroll
    for (int it = 0; it < 8; it++) {
        int u = tid + 128 * it;
        int mat = u >> 9;                  // 0 = Q, 1 = K
        int idx = u & 511;
        int row = idx >> 3, c16 = idx & 7;
        uint32_t dst = sb + (mat ? AT_SK : AT_SQ) + row * 128 +
                       ((uint32_t)(c16 * 16) ^ (uint32_t)((row & 7) << 4));
        if (row < Leff) {
            const __half* src = QKV + (size_t)ridx[row] * QKV_DIM + hoff +
                                (mat ? HIDDEN_DIM : 0) + c16 * 8;
            cp16(dst, src);
        } else {
            asm volatile("st.shared.v4.b32 [%0], {%1,%1,%1,%1};"
                         :: "r"(dst), "r"(0u) : "memory");
        }
    }
    cp_commit();
    cp_wait<0>();
    __syncthreads();

    // Phase 2a: ALL 4 warps run the score mma loop (Q,K smem reads)
    float cfr[8][4];
#pragma unroll
    for (int nt = 0; nt < 8; nt++)
#pragma unroll
        for (int r = 0; r < 4; r++) cfr[nt][r] = 0.f;
    {
        const uint32_t swl = (uint32_t)((lane & 7) << 4);
        const uint32_t abase = sb + AT_SQ + (uint32_t)(16 * wid + (lane & 15)) * 128;
        const uint32_t ahi = (uint32_t)(((lane >> 4) & 1) * 16);
        const int brow = (lane & 7) + ((lane >> 4) & 1) * 8;
        const uint32_t bhi = (uint32_t)(((lane >> 3) & 1) * 16);

#pragma unroll
        for (int kf = 0; kf < 4; kf++) {
            uint32_t a0, a1, a2, a3, b[4][4];
            ldsm4(a0, a1, a2, a3, abase + (((uint32_t)(kf * 32) + ahi) ^ swl));
#pragma unroll
            for (int bt = 0; bt < 4; bt++)
                ldsm4(b[bt][0], b[bt][1], b[bt][2], b[bt][3],
                      sb + AT_SK + (uint32_t)(bt * 16 + brow) * 128 +
                          (((uint32_t)(kf * 32) + bhi) ^ swl));
#pragma unroll
            for (int nt = 0; nt < 8; nt++)
                mma16816(cfr[nt], a0, a1, a2, a3,
                         b[nt >> 1][(nt & 1) * 2], b[nt >> 1][(nt & 1) * 2 + 1]);
        }
    }
    __syncthreads();   // all warps done reading Q tile -> safe to overwrite with V

    // Phase 2b: issue V gather into old Q region, overlapping softmax below.
#pragma unroll
    for (int it = 0; it < 4; it++) {
        int u = tid + 128 * it;            // 512 units
        int row = u >> 3, c16 = u & 7;
        uint32_t dst = sb + AT_SQ + row * 128 + c16 * 16;
        if (row < Leff) {
            cp16(dst, QKV + (size_t)ridx[row] * QKV_DIM + 2 * HIDDEN_DIM + hoff + c16 * 8);
        } else {
            asm volatile("st.shared.v4.b32 [%0], {%1,%1,%1,%1};"
                         :: "r"(dst), "r"(0u) : "memory");
        }
    }
    cp_commit();

    // Phase 2c: softmax on fragments, write probs fp16
    {
        float m0 = -1e30f, m1 = -1e30f;
#pragma unroll
        for (int nt = 0; nt < 8; nt++)
#pragma unroll
            for (int rg = 0; rg < 2; rg++) {
                int col = nt * 8 + (lane & 3) * 2 + rg;
                if (col < Leff) {
                    m0 = fmaxf(m0, cfr[nt][rg] * 0.125f);
                    m1 = fmaxf(m1, cfr[nt][2 + rg] * 0.125f);
                }
            }
        m0 = fmaxf(m0, __shfl_xor_sync(0xffffffffu, m0, 1));
        m0 = fmaxf(m0, __shfl_xor_sync(0xffffffffu, m0, 2));
        m1 = fmaxf(m1, __shfl_xor_sync(0xffffffffu, m1, 1));
        m1 = fmaxf(m1, __shfl_xor_sync(0xffffffffu, m1, 2));

        float s0 = 0.f, s1 = 0.f;
#pragma unroll
        for (int nt = 0; nt < 8; nt++)
#pragma unroll
            for (int rg = 0; rg < 2; rg++) {
                int col = nt * 8 + (lane & 3) * 2 + rg;
                float e0 = (col < Leff) ? __expf(cfr[nt][rg] * 0.125f - m0) : 0.f;
                float e1 = (col < Leff) ? __expf(cfr[nt][2 + rg] * 0.125f - m1) : 0.f;
                cfr[nt][rg] = e0;
                cfr[nt][2 + rg] = e1;
                s0 += e0; s1 += e1;
            }
        s0 += __shfl_xor_sync(0xffffffffu, s0, 1);
        s0 += __shfl_xor_sync(0xffffffffu, s0, 2);
        s1 += __shfl_xor_sync(0xffffffffu, s1, 1);
        s1 += __shfl_xor_sync(0xffffffffu, s1, 2);
        float i0 = 1.f / s0, i1 = 1.f / s1;

        int row0 = 16 * wid + (lane >> 2);
#pragma unroll
        for (int nt = 0; nt < 8; nt++)
#pragma unroll
            for (int rg = 0; rg < 2; rg++) {
                int col = nt * 8 + (lane & 3) * 2 + rg;
                psh[row0 * 72 + col] = __float2half(cfr[nt][rg] * i0);
                psh[(row0 + 8) * 72 + col] = __float2half(cfr[nt][2 + rg] * i1);
            }
    }
    __syncthreads();

    // Phase 3: column mean over valid query rows (V loads still in flight)
    if (tid < 64) {
        float s = 0.f;
        for (int ll = 0; ll < Leff; ll++) s += __half2float(psh[ll * 72 + tid]);
        wsum[tid] = s / (float)Leff;
    }
    cp_wait<0>();      // V tile resident
    __syncthreads();

    // Phase 4: pooled[d] = sum_{m<Leff} wsum[m] * V[m][d] from smem
    {
        int pt = tid >> 6, d = tid & 63;
        float acc = 0.f;
        for (int m = pt; m < Leff; m += 2)
            acc = fmaf(wsum[m], __half2float(vsh[m * 64 + d]), acc);
        part[pt * 64 + d] = acc;
    }
    __syncthreads();
    if (tid < 64)
        pooled[(size_t)c * HIDDEN_DIM + hoff + tid] =
            __float2half(part[tid] + part[64 + tid]);
}

// ---------------------------------------------------------------------------
// Launch (single stream; convert merged into weights launch)
// ---------------------------------------------------------------------------
extern "C" void kernel_launch(void* const* d_in, const int* in_sizes, int n_in,
                              void* d_out, int out_size) {
    const float* chunk = (const float*)d_in[0];
    const float* Wq   = (const float*)d_in[1];
    const float* bq   = (const float*)d_in[2];
    const float* Wk   = (const float*)d_in[3];
    const float* bk   = (const float*)d_in[4];
    const float* Wv   = (const float*)d_in[5];
    const float* bv   = (const float*)d_in[6];
    const float* W_in = (const float*)d_in[7];
    const float* b_in = (const float*)d_in[8];
    const float* Wo   = (const float*)d_in[9];
    const float* bo   = (const float*)d_in[10];
    const float* Wout = (const float*)d_in[11];
    const float* bout = (const float*)d_in[12];
    const void*  cidx = d_in[13];
    const void*  clen = d_in[14];
    float* out = (float*)d_out;

    __half *pQKV, *pPooled;
    float *pbeff, *pbfinal;
    cudaGetSymbolAddress((void**)&pQKV, g_QKV);
    cudaGetSymbolAddress((void**)&pPooled, g_pooled);
    cudaGetSymbolAddress((void**)&pbeff, g_beff);
    cudaGetSymbolAddress((void**)&pbfinal, g_bfinal);

    static bool attr_set = false;
    if (!attr_set) {
        cudaFuncSetAttribute(qkv_mma_kernel, cudaFuncAttributeMaxDynamicSharedMemorySize,
                             SMEM_MMA);
        cudaFuncSetAttribute(out_mma_kernel, cudaFuncAttributeMaxDynamicSharedMemorySize,
                             SMEM_MMA);
        attr_set = true;
    }

    // 0+1) dtype detection + combined biases (merged)
    setup_kernel<<<(QKV_DIM + OUTPUT_DIM + 1 + 255) / 256, 256>>>(
        (const int*)cidx, (const int*)clen,
        W_in, b_in, bq, bk, bv, Wout, bo, bout, pbeff, pbfinal);

    // 2) merged small GEMMs + chunk convert (concurrent in one launch), then reduce
    weights_part_kernel<<<dim3(INPUT_DIM / 128, HIDDEN_DIM / 128, 16 + CONV_Z), 256>>>(
        W_in, Wq, Wk, Wv, Wout, Wo, chunk);
    reduce_weights_kernel<<<(unsigned)((N_WEFF4 + N_WFIN4 + 255) / 256), 256>>>();

    // 3) QKV projection (8-warp R11 config, fp16 output)
    qkv_mma_kernel<<<dim3(QKV_DIM / 128, M_PAD / 128), 256, SMEM_MMA>>>(pbeff, pQKV);

    // 4) fused attention + masked mean pool (V prefetch overlapped)
    attn_pool_kernel<<<dim3(NUM_CELLS, NUM_HEADS), 128>>>(pQKV, cidx, clen, pPooled);

    // 5) final projection via mma
    out_mma_kernel<<<dim3(OUTPUT_DIM / 128, NUM_CELLS / 128), 256, SMEM_MMA>>>(pbfinal, out);
}